// round 2
// baseline (speedup 1.0000x reference)
#include <cuda_runtime.h>
#include <cuda_bf16.h>
#include <math.h>

#define T_STEPS 2048
#define BATCH 32
#define INF 128
#define HID 256

// ---------------- scratch (static device allocations are the sanctioned path) ----
__device__ float g_A0[(size_t)T_STEPS * BATCH * INF];            // 33.5 MB  [t*B+b][f]
__device__ float g_XWA[(size_t)T_STEPS * BATCH * 1024];          // 268 MB
__device__ float g_XWB[(size_t)T_STEPS * BATCH * 1024];          // 268 MB
__device__ float g_OUT0[(size_t)T_STEPS * BATCH * 512];          // 134 MB
__device__ float g_Hbuf[2 * 2 * BATCH * HID];                    // [parity][dir][b][j]
__device__ float g_LAST[BATCH * 512];                            // fwd h(T-1) in cols 0:256
__device__ float g_XWB1L[BATCH * 1024];                          // xw of layer1-bwd @ t=T-1
__device__ unsigned g_count = 0;
__device__ unsigned g_gen = 0;

__device__ __forceinline__ float sigf(float x) { return 1.0f / (1.0f + expf(-x)); }

// ---------------- transpose x[B,1,IN,T] -> A0[(t*B+b), f] ------------------------
__global__ void transpose_x(const float* __restrict__ x, float* __restrict__ A0) {
    __shared__ float tile[32][33];
    int b = blockIdx.z;
    int f0 = blockIdx.y * 32, t0 = blockIdx.x * 32;
    int tx = threadIdx.x, ty = threadIdx.y;
#pragma unroll
    for (int i = 0; i < 32; i += 8)
        tile[ty + i][tx] = x[((size_t)b * INF + (f0 + ty + i)) * T_STEPS + t0 + tx];
    __syncthreads();
#pragma unroll
    for (int i = 0; i < 32; i += 8)
        A0[(((size_t)(t0 + ty + i)) * BATCH + b) * INF + f0 + tx] = tile[tx][ty + i];
}

// ---------------- fp32 GEMM: C[M,N] = A[M,K] * W[N,K]^T + bias[N] ----------------
// BM=BN=128, BK=16, 256 threads, 8x8 per-thread tile.
__global__ void __launch_bounds__(256) gemm_bias(
    const float* __restrict__ A, const float* __restrict__ W,
    const float* __restrict__ bias, float* __restrict__ C,
    int M, int N, int K)
{
    __shared__ float As[16][132];
    __shared__ float Bs[16][132];
    const int bn = blockIdx.x * 128;
    const int bm = blockIdx.y * 128;
    const int tid = threadIdx.x;
    const int tx = tid & 15, ty = tid >> 4;
    const int lrow = tid >> 2;
    const int lk = (tid & 3) << 2;

    float acc[8][8];
#pragma unroll
    for (int i = 0; i < 8; i++)
#pragma unroll
        for (int j = 0; j < 8; j++) acc[i][j] = 0.f;

    for (int k0 = 0; k0 < K; k0 += 16) {
#pragma unroll
        for (int h = 0; h < 2; ++h) {
            int m = bm + lrow + h * 64;
            float4 v = (m < M) ? *(const float4*)&A[(size_t)m * K + k0 + lk]
                               : make_float4(0.f, 0.f, 0.f, 0.f);
            As[lk + 0][lrow + h * 64] = v.x; As[lk + 1][lrow + h * 64] = v.y;
            As[lk + 2][lrow + h * 64] = v.z; As[lk + 3][lrow + h * 64] = v.w;
            int n = bn + lrow + h * 64;
            float4 wv = *(const float4*)&W[(size_t)n * K + k0 + lk];
            Bs[lk + 0][lrow + h * 64] = wv.x; Bs[lk + 1][lrow + h * 64] = wv.y;
            Bs[lk + 2][lrow + h * 64] = wv.z; Bs[lk + 3][lrow + h * 64] = wv.w;
        }
        __syncthreads();
#pragma unroll
        for (int k = 0; k < 16; ++k) {
            float a[8], bb[8];
            *(float4*)&a[0]  = *(const float4*)&As[k][ty * 8];
            *(float4*)&a[4]  = *(const float4*)&As[k][ty * 8 + 4];
            *(float4*)&bb[0] = *(const float4*)&Bs[k][tx * 8];
            *(float4*)&bb[4] = *(const float4*)&Bs[k][tx * 8 + 4];
#pragma unroll
            for (int i = 0; i < 8; i++)
#pragma unroll
                for (int j = 0; j < 8; j++) acc[i][j] += a[i] * bb[j];
        }
        __syncthreads();
    }
#pragma unroll
    for (int i = 0; i < 8; i++) {
        int row = bm + ty * 8 + i;
        if (row >= M) continue;
#pragma unroll
        for (int j = 0; j < 8; j += 4) {
            int col = bn + tx * 8 + j;
            float4 o;
            o.x = acc[i][j + 0] + bias[col + 0];
            o.y = acc[i][j + 1] + bias[col + 1];
            o.z = acc[i][j + 2] + bias[col + 2];
            o.w = acc[i][j + 3] + bias[col + 3];
            *(float4*)&C[(size_t)row * N + col] = o;
        }
    }
}

// ---------------- persistent recurrent kernel --------------------------------
// LAYER==0: 128 blocks = 2 dirs x (8 hidden-chunks of 32 units) x (8 batch-chunks of 4)
// LAYER==1: 128 blocks = 1 dir  x (16 hidden-chunks of 16 units) x (8 batch-chunks of 4)
template <int LAYER>
__global__ void __launch_bounds__(256, 1) rec_kernel(
    const float* __restrict__ xwF, const float* __restrict__ xwB,
    const float* __restrict__ whhF, const float* __restrict__ whhB,
    float* __restrict__ out)
{
    extern __shared__ float sm[];
    const int tid = threadIdx.x;
    const int bid = blockIdx.x;
    const unsigned nb = gridDim.x;

    constexpr int J    = (LAYER == 0) ? 32 : 16;
    constexpr int Jlog = (LAYER == 0) ? 5 : 4;
    constexpr int ROWS = 4 * J;                 // 128 / 64 gate rows per block
    constexpr int OPT  = (LAYER == 0) ? 2 : 1;  // outputs per thread
    constexpr int BSTEP = 256 / ROWS;           // 2 / 4

    int dir, hc, bc;
    if (LAYER == 0) { dir = bid >> 6; int sub = bid & 63; hc = sub >> 3; bc = sub & 7; }
    else            { dir = 0; hc = bid >> 3; bc = bid & 7; }
    const int j0 = hc * J;
    const int b0 = bc * 4;

    float* Wsm = sm;                       // ROWS x 260 (padded)
    float* hsm = Wsm + ROWS * 260;         // 4 x 256
    float* gsm = hsm + 1024;               // 4 x ROWS

    const float* xw  = dir ? xwB  : xwF;
    const float* whh = dir ? whhB : whhF;

    // stage W_hh slice into smem (rows: gate-major within our hidden chunk)
    for (int idx = tid; idx < ROWS * 64; idx += 256) {
        int r = idx >> 6, k4 = (idx & 63) << 2;
        int gr = ((r >> Jlog) << 8) + j0 + (r & (J - 1));
        *(float4*)&Wsm[r * 260 + k4] = *(const float4*)&whh[(size_t)gr * 256 + k4];
    }

    const int r = tid & (ROWS - 1);
    const int gr = ((r >> Jlog) << 8) + j0 + (r & (J - 1));
    const int bl0 = tid / ROWS;

    const int UN = 4 * J;                  // units owned by this block (b x j pairs)
    const int bu = tid >> Jlog;
    const int jj = tid & (J - 1);
    float creg = 0.f;

    for (int t = 0; t < T_STEPS; ++t) {
        const int tr = dir ? (T_STEPS - 1 - t) : t;

        // load h_prev (parity t&1) — must bypass L1 (other SMs wrote it)
        {
            const float* Hrd = &g_Hbuf[((t & 1) * 2 + dir) * (BATCH * HID)];
            int bb = tid >> 6, k4 = (tid & 63) << 2;
            float4 hv = __ldcg((const float4*)&Hrd[(b0 + bb) * HID + k4]);
            *(float4*)&hsm[bb * 256 + k4] = hv;
        }
        __syncthreads();

        float acc0, acc1 = 0.f;
        {
            size_t base = ((size_t)tr * BATCH + b0) * 1024 + gr;
            acc0 = xw[base + (size_t)bl0 * 1024];
            if (OPT == 2) acc1 = xw[base + (size_t)(bl0 + BSTEP) * 1024];
        }
        const float4* Wp  = (const float4*)&Wsm[r * 260];
        const float4* h0p = (const float4*)&hsm[bl0 * 256];
        const float4* h1p = (const float4*)&hsm[((bl0 + BSTEP) & 3) * 256];
#pragma unroll 8
        for (int k4 = 0; k4 < 64; ++k4) {
            float4 w = Wp[k4];
            float4 h0 = h0p[k4];
            acc0 += w.x * h0.x + w.y * h0.y + w.z * h0.z + w.w * h0.w;
            if (OPT == 2) {
                float4 h1 = h1p[k4];
                acc1 += w.x * h1.x + w.y * h1.y + w.z * h1.z + w.w * h1.w;
            }
        }
        gsm[bl0 * ROWS + r] = acc0;
        if (OPT == 2) gsm[(bl0 + BSTEP) * ROWS + r] = acc1;
        __syncthreads();

        if (tid < UN) {
            float gi = gsm[bu * ROWS + 0 * J + jj];
            float gf = gsm[bu * ROWS + 1 * J + jj];
            float gg = gsm[bu * ROWS + 2 * J + jj];
            float go = gsm[bu * ROWS + 3 * J + jj];
            float ii = sigf(gi), ff = sigf(gf), oo = sigf(go);
            creg = ff * creg + ii * tanhf(gg);
            float h = oo * tanhf(creg);
            g_Hbuf[(((t + 1) & 1) * 2 + dir) * (BATCH * HID) + (b0 + bu) * HID + (j0 + jj)] = h;
            if (LAYER == 0) {
                out[((size_t)tr * BATCH + (b0 + bu)) * 512 + (dir << 8) + j0 + jj] = h;
            } else if (t == T_STEPS - 1) {
                out[(b0 + bu) * 512 + j0 + jj] = h;   // g_LAST fwd half
            }
        }
        __threadfence();
        // ---- software grid barrier (all 128 blocks resident) ----
        __syncthreads();
        if (tid == 0) {
            unsigned gen = *((volatile unsigned*)&g_gen);
            if (atomicAdd(&g_count, 1u) == nb - 1u) {
                g_count = 0;
                __threadfence();
                atomicExch((unsigned*)&g_gen, gen + 1u);
            } else {
                while (*((volatile unsigned*)&g_gen) == gen) { }
            }
        }
        __syncthreads();
    }
}

// ---------------- final: hb1(T-1) one-step + FC -------------------------------
__global__ void final_kernel(const float* __restrict__ fc_w, const float* __restrict__ fc_b,
                             float* __restrict__ outp)
{
    __shared__ float last[512];
    int b = blockIdx.x, tid = threadIdx.x;   // 128 threads
    for (int j = tid; j < 256; j += 128) {
        last[j] = g_LAST[b * 512 + j];
        float gi = g_XWB1L[b * 1024 + j];
        float gg = g_XWB1L[b * 1024 + 512 + j];
        float go = g_XWB1L[b * 1024 + 768 + j];
        float c = sigf(gi) * tanhf(gg);      // c0 = 0 -> f*c0 vanishes
        last[256 + j] = sigf(go) * tanhf(c);
    }
    __syncthreads();
    float acc = fc_b[tid];
    const float4* w  = (const float4*)&fc_w[(size_t)tid * 512];
    const float4* l4 = (const float4*)last;
#pragma unroll 8
    for (int k = 0; k < 128; ++k) {
        float4 ww = w[k]; float4 ll = l4[k];
        acc += ww.x * ll.x + ww.y * ll.y + ww.z * ll.z + ww.w * ll.w;
    }
    outp[b * 128 + tid] = acc;
}

// ---------------- launch ------------------------------------------------------
extern "C" void kernel_launch(void* const* d_in, const int* in_sizes, int n_in,
                              void* d_out, int out_size)
{
    const float* x     = (const float*)d_in[0];
    const float* wih0f = (const float*)d_in[1];
    const float* whh0f = (const float*)d_in[2];
    const float* b0f   = (const float*)d_in[3];
    const float* wih0b = (const float*)d_in[4];
    const float* whh0b = (const float*)d_in[5];
    const float* b0b   = (const float*)d_in[6];
    const float* wih1f = (const float*)d_in[7];
    const float* whh1f = (const float*)d_in[8];
    const float* b1f   = (const float*)d_in[9];
    const float* wih1b = (const float*)d_in[10];
    const float* whh1b = (const float*)d_in[11];
    const float* b1b   = (const float*)d_in[12];
    const float* fcw   = (const float*)d_in[13];
    const float* fcb   = (const float*)d_in[14];
    float* outp = (float*)d_out;

    float *A0, *XWA, *XWB, *OUT0, *Hb, *LAST, *XWB1L;
    cudaGetSymbolAddress((void**)&A0,    g_A0);
    cudaGetSymbolAddress((void**)&XWA,   g_XWA);
    cudaGetSymbolAddress((void**)&XWB,   g_XWB);
    cudaGetSymbolAddress((void**)&OUT0,  g_OUT0);
    cudaGetSymbolAddress((void**)&Hb,    g_Hbuf);
    cudaGetSymbolAddress((void**)&LAST,  g_LAST);
    cudaGetSymbolAddress((void**)&XWB1L, g_XWB1L);

    cudaFuncSetAttribute(rec_kernel<0>, cudaFuncAttributeMaxDynamicSharedMemorySize, 160 * 1024);
    cudaFuncSetAttribute(rec_kernel<1>, cudaFuncAttributeMaxDynamicSharedMemorySize, 160 * 1024);

    // 1) transpose x -> A0
    {
        dim3 tb(32, 8);
        dim3 tg(T_STEPS / 32, INF / 32, BATCH);
        transpose_x<<<tg, tb>>>(x, A0);
    }
    // 2) layer-0 input projections (both directions)
    {
        dim3 gb(1024 / 128, (T_STEPS * BATCH) / 128);
        gemm_bias<<<gb, 256>>>(A0, wih0f, b0f, XWA, T_STEPS * BATCH, 1024, INF);
        gemm_bias<<<gb, 256>>>(A0, wih0b, b0b, XWB, T_STEPS * BATCH, 1024, INF);
    }
    // 3) layer-0 bidirectional recurrence -> OUT0
    cudaMemsetAsync(Hb, 0, 2 * 2 * BATCH * HID * sizeof(float));
    {
        size_t smem = (size_t)(128 * 260 + 1024 + 512) * sizeof(float);
        rec_kernel<0><<<128, 256, smem>>>(XWA, XWB, whh0f, whh0b, OUT0);
    }
    // 4) layer-1 fwd input projection (reuse XWA)
    {
        dim3 gb(1024 / 128, (T_STEPS * BATCH) / 128);
        gemm_bias<<<gb, 256>>>(OUT0, wih1f, b1f, XWA, T_STEPS * BATCH, 1024, 512);
    }
    // 5) layer-1 fwd recurrence -> g_LAST cols 0:256
    cudaMemsetAsync(Hb, 0, 2 * 2 * BATCH * HID * sizeof(float));
    {
        size_t smem = (size_t)(64 * 260 + 1024 + 256) * sizeof(float);
        rec_kernel<1><<<128, 256, smem>>>(XWA, XWA, whh1f, whh1f, LAST);
    }
    // 6) layer-1 bwd needs only its FIRST step (t = T-1): one 32-row GEMM
    {
        dim3 gs(1024 / 128, 1);
        gemm_bias<<<gs, 256>>>(OUT0 + (size_t)(T_STEPS - 1) * BATCH * 512,
                               wih1b, b1b, XWB1L, BATCH, 1024, 512);
    }
    // 7) hb1 elementwise + FC
    final_kernel<<<BATCH, 128>>>(fcw, fcb, outp);
}

// round 3
// speedup vs baseline: 1.1469x; 1.1469x over previous
#include <cuda_runtime.h>
#include <math.h>
#include <cstdint>

#define T_STEPS 2048
#define BATCH 32
#define INF 128
#define HID 256

typedef unsigned long long ull;

// ---------------- scratch ------------------------------------------------------
__device__ float g_A0[(size_t)T_STEPS * BATCH * INF];
__device__ float g_XWA[(size_t)T_STEPS * BATCH * 1024];
__device__ float g_XWB[(size_t)T_STEPS * BATCH * 1024];
__device__ float g_OUT0[(size_t)T_STEPS * BATCH * 512];
__device__ float g_LAST[BATCH * 512];
__device__ float g_XWB1L[BATCH * 1024];

__device__ __forceinline__ float sigf(float x) {
    return __fdividef(1.0f, 1.0f + __expf(-x));
}
__device__ __forceinline__ float tanhf_fast(float x) {
    float e = __expf(2.0f * x);
    return 1.0f - __fdividef(2.0f, e + 1.0f);
}
__device__ __forceinline__ uint32_t smem_u32(const void* p) {
    uint32_t a;
    asm("{ .reg .u64 t; cvta.to.shared.u64 t, %1; cvt.u32.u64 %0, t; }" : "=r"(a) : "l"(p));
    return a;
}
__device__ __forceinline__ ull pack2(float x) {
    ull r; asm("mov.b64 %0, {%1, %1};" : "=l"(r) : "f"(x)); return r;
}
__device__ __forceinline__ void fma2(ull& d, ull a, ull b) {
    asm("fma.rn.f32x2 %0, %1, %2, %0;" : "+l"(d) : "l"(a), "l"(b));
}
__device__ __forceinline__ float2 unpack2(ull v) {
    float2 f; asm("mov.b64 {%0, %1}, %2;" : "=f"(f.x), "=f"(f.y) : "l"(v)); return f;
}
__device__ __forceinline__ void mbar_wait_cluster(uint32_t addr, unsigned phase) {
    asm volatile(
        "{\n\t.reg .pred P;\n\t"
        "WAIT_%=:\n\t"
        "mbarrier.try_wait.parity.acquire.cluster.shared::cta.b64 P, [%0], %1, 0x989680;\n\t"
        "@P bra.uni DONE_%=;\n\t"
        "bra.uni WAIT_%=;\n\t"
        "DONE_%=:\n\t}"
        :: "r"(addr), "r"(phase) : "memory");
}

// ---------------- transpose x[B,1,IN,T] -> A0[(t*B+b), f] ------------------------
__global__ void transpose_x(const float* __restrict__ x, float* __restrict__ A0) {
    __shared__ float tile[32][33];
    int b = blockIdx.z;
    int f0 = blockIdx.y * 32, t0 = blockIdx.x * 32;
    int tx = threadIdx.x, ty = threadIdx.y;
#pragma unroll
    for (int i = 0; i < 32; i += 8)
        tile[ty + i][tx] = x[((size_t)b * INF + (f0 + ty + i)) * T_STEPS + t0 + tx];
    __syncthreads();
#pragma unroll
    for (int i = 0; i < 32; i += 8)
        A0[(((size_t)(t0 + ty + i)) * BATCH + b) * INF + f0 + tx] = tile[tx][ty + i];
}

// ---------------- fp32 GEMM: C[M,N] = A[M,K] * W[N,K]^T + bias[N] ----------------
__global__ void __launch_bounds__(256) gemm_bias(
    const float* __restrict__ A, const float* __restrict__ W,
    const float* __restrict__ bias, float* __restrict__ C,
    int M, int N, int K)
{
    __shared__ float As[16][132];
    __shared__ float Bs[16][132];
    const int bn = blockIdx.x * 128;
    const int bm = blockIdx.y * 128;
    const int tid = threadIdx.x;
    const int tx = tid & 15, ty = tid >> 4;
    const int lrow = tid >> 2;
    const int lk = (tid & 3) << 2;

    float acc[8][8];
#pragma unroll
    for (int i = 0; i < 8; i++)
#pragma unroll
        for (int j = 0; j < 8; j++) acc[i][j] = 0.f;

    for (int k0 = 0; k0 < K; k0 += 16) {
#pragma unroll
        for (int h = 0; h < 2; ++h) {
            int m = bm + lrow + h * 64;
            float4 v = (m < M) ? *(const float4*)&A[(size_t)m * K + k0 + lk]
                               : make_float4(0.f, 0.f, 0.f, 0.f);
            As[lk + 0][lrow + h * 64] = v.x; As[lk + 1][lrow + h * 64] = v.y;
            As[lk + 2][lrow + h * 64] = v.z; As[lk + 3][lrow + h * 64] = v.w;
            int n = bn + lrow + h * 64;
            float4 wv = *(const float4*)&W[(size_t)n * K + k0 + lk];
            Bs[lk + 0][lrow + h * 64] = wv.x; Bs[lk + 1][lrow + h * 64] = wv.y;
            Bs[lk + 2][lrow + h * 64] = wv.z; Bs[lk + 3][lrow + h * 64] = wv.w;
        }
        __syncthreads();
#pragma unroll
        for (int k = 0; k < 16; ++k) {
            float a[8], bb[8];
            *(float4*)&a[0]  = *(const float4*)&As[k][ty * 8];
            *(float4*)&a[4]  = *(const float4*)&As[k][ty * 8 + 4];
            *(float4*)&bb[0] = *(const float4*)&Bs[k][tx * 8];
            *(float4*)&bb[4] = *(const float4*)&Bs[k][tx * 8 + 4];
#pragma unroll
            for (int i = 0; i < 8; i++)
#pragma unroll
                for (int j = 0; j < 8; j++) acc[i][j] += a[i] * bb[j];
        }
        __syncthreads();
    }
#pragma unroll
    for (int i = 0; i < 8; i++) {
        int row = bm + ty * 8 + i;
        if (row >= M) continue;
#pragma unroll
        for (int j = 0; j < 8; j += 4) {
            int col = bn + tx * 8 + j;
            float4 o;
            o.x = acc[i][j + 0] + bias[col + 0];
            o.y = acc[i][j + 1] + bias[col + 1];
            o.z = acc[i][j + 2] + bias[col + 2];
            o.w = acc[i][j + 3] + bias[col + 3];
            *(float4*)&C[(size_t)row * N + col] = o;
        }
    }
}

// ---------------- cluster-based persistent recurrence ----------------------------
// 16 independent clusters of 8 CTAs. Cluster = (dir, batch-chunk); CTA rank = 32-unit
// hidden chunk. h exchanged each step via DSMEM multicast stores + mbarrier,
// double-buffered by step parity. W_hh lives in registers; matvec uses fma.rn.f32x2
// with batch pairs packed as f32x2.
template <int LAYER>
__global__ void __cluster_dims__(8, 1, 1) __launch_bounds__(256, 1) rec_kernel(
    const float* __restrict__ xwF, const float* __restrict__ xwB,
    const float* __restrict__ whhF, const float* __restrict__ whhB,
    float* __restrict__ out)
{
    constexpr int NB    = (LAYER == 0) ? 4 : 2;   // batches per cluster
    constexpr int NPAIR = NB / 2;
    constexpr int F4    = NB * 8;                 // float4s sent per peer
    constexpr int STOR  = 8 * F4;                 // storer threads (=arrivals/barrier)

    __shared__ alignas(16) float hp[2][NPAIR][256][2];   // [parity][pair][k][lane]
    __shared__ float gpart[2][128][NB];                  // [k-half][row][batch]
    __shared__ alignas(16) float stage[NPAIR][32][2];    // [pair][j][lane]
    __shared__ alignas(8) unsigned long long mbar[2];

    const int tid  = threadIdx.x;
    const unsigned rank = blockIdx.x & 7;
    const unsigned cl   = blockIdx.x >> 3;

    int dir, b0;
    if (LAYER == 0) { dir = cl >> 3; b0 = (cl & 7) * 4; }
    else            { dir = 0;       b0 = cl * 2; }
    const int j0 = rank * 32;

    const float* xw  = dir ? xwB  : xwF;
    const float* whh = dir ? whhB : whhF;

    const int r    = tid & 127;          // gate row within chunk (4 gates x 32 units)
    const int half = tid >> 7;           // k-half: [half*128, half*128+128)
    const int gr   = ((r >> 5) << 8) + j0 + (r & 31);   // row in W_hh / xw

    // W_hh slice -> registers (128 floats per thread)
    float w[128];
#pragma unroll
    for (int i = 0; i < 32; ++i) {
        float4 v = *(const float4*)&whh[(size_t)gr * 256 + half * 128 + i * 4];
        w[4 * i + 0] = v.x; w[4 * i + 1] = v.y; w[4 * i + 2] = v.z; w[4 * i + 3] = v.w;
    }

    // init h buffers to zero + barriers
    for (int idx = tid; idx < 2 * NPAIR * 256 * 2; idx += 256) ((float*)hp)[idx] = 0.f;
    if (tid == 0) {
        asm volatile("mbarrier.init.shared.b64 [%0], %1;" :: "r"(smem_u32(&mbar[0])), "r"(STOR));
        asm volatile("mbarrier.init.shared.b64 [%0], %1;" :: "r"(smem_u32(&mbar[1])), "r"(STOR));
    }
    __syncthreads();
    asm volatile("barrier.cluster.arrive.aligned;" ::: "memory");
    asm volatile("barrier.cluster.wait.aligned;" ::: "memory");

    unsigned ph[2] = {0, 0};
    float c_state = 0.f;
    const int cb = tid >> 5, cj = tid & 31;     // cell-update mapping (tid < NB*32)
    const uint32_t mb_loc[2] = { smem_u32(&mbar[0]), smem_u32(&mbar[1]) };

    for (int t = 0; t < T_STEPS; ++t) {
        const int tr = dir ? (T_STEPS - 1 - t) : t;
        const int p = t & 1, pn = p ^ 1;

        // prefetch xw for this step (issued before the wait; latency hidden)
        float xa = 0.f, xb = 0.f;
        if (NB == 4 || half == 0) {
            size_t xbase = ((size_t)tr * BATCH + b0 + 2 * half) * 1024 + gr;
            xa = __ldcs(&xw[xbase]);
            xb = __ldcs(&xw[xbase + 1024]);
        }

        if (t > 0) { mbar_wait_cluster(mb_loc[p], ph[p]); ph[p] ^= 1; }

        // ---- matvec: gates[r][b] += sum_k W[r][k] * h[b][k], f32x2 over batch pairs
        ull acc0[NPAIR], acc1[NPAIR];
#pragma unroll
        for (int pr = 0; pr < NPAIR; ++pr) { acc0[pr] = 0ull; acc1[pr] = 0ull; }
        const ulonglong2* hv = (const ulonglong2*)&hp[p][0][half * 128][0];
#pragma unroll
        for (int i = 0; i < 64; ++i) {
            ull w0 = pack2(w[2 * i]);
            ull w1 = pack2(w[2 * i + 1]);
#pragma unroll
            for (int pr = 0; pr < NPAIR; ++pr) {
                ulonglong2 h2 = hv[pr * 128 + i];   // 2 k-values x 1 batch-pair
                fma2(acc0[pr], w0, h2.x);
                fma2(acc1[pr], w1, h2.y);
            }
        }
#pragma unroll
        for (int pr = 0; pr < NPAIR; ++pr) {
            float2 a = unpack2(acc0[pr]);
            float2 b = unpack2(acc1[pr]);
            float lo = a.x + b.x, hi = a.y + b.y;
            if (pr == half) { lo += xa; hi += xb; }
            gpart[half][r][2 * pr + 0] = lo;
            gpart[half][r][2 * pr + 1] = hi;
        }
        __syncthreads();

        // ---- cell update (one thread per (batch, unit))
        if (tid < NB * 32) {
            float gi = gpart[0][cj][cb]      + gpart[1][cj][cb];
            float gf = gpart[0][32 + cj][cb] + gpart[1][32 + cj][cb];
            float gg = gpart[0][64 + cj][cb] + gpart[1][64 + cj][cb];
            float go = gpart[0][96 + cj][cb] + gpart[1][96 + cj][cb];
            float ii = sigf(gi), ff = sigf(gf), oo = sigf(go);
            c_state = ff * c_state + ii * tanhf_fast(gg);
            float h = oo * tanhf_fast(c_state);
            stage[cb >> 1][cj][cb & 1] = h;
            if (LAYER == 0)
                out[((size_t)tr * BATCH + (b0 + cb)) * 512 + (dir << 8) + j0 + cj] = h;
            else if (t == T_STEPS - 1)
                out[(b0 + cb) * 512 + j0 + cj] = h;
        }
        __syncthreads();

        // ---- DSMEM broadcast of our h chunk to all 8 cluster CTAs ----
        if (t < T_STEPS - 1 && tid < STOR) {
            const int peer = tid / F4;
            const int i    = tid & (F4 - 1);
            const int pair = i >> 4;
            const int jl   = (i & 15) * 2;
            float4 val = ((const float4*)stage)[i];
            uint32_t laddr = smem_u32(&hp[pn][pair][j0 + jl][0]);
            uint32_t raddr, rmb;
            asm("mapa.shared::cluster.u32 %0, %1, %2;" : "=r"(raddr) : "r"(laddr), "r"(peer));
            asm volatile("st.shared::cluster.v4.f32 [%0], {%1, %2, %3, %4};"
                         :: "r"(raddr), "f"(val.x), "f"(val.y), "f"(val.z), "f"(val.w)
                         : "memory");
            asm("mapa.shared::cluster.u32 %0, %1, %2;" : "=r"(rmb) : "r"(mb_loc[pn]), "r"(peer));
            asm volatile("mbarrier.arrive.release.cluster.shared::cluster.b64 _, [%0];"
                         :: "r"(rmb) : "memory");
        }
    }
}

// ---------------- final: hb1(T-1) one-step + FC -------------------------------
__global__ void final_kernel(const float* __restrict__ fc_w, const float* __restrict__ fc_b,
                             float* __restrict__ outp)
{
    __shared__ float last[512];
    int b = blockIdx.x, tid = threadIdx.x;   // 128 threads
    for (int j = tid; j < 256; j += 128) {
        last[j] = g_LAST[b * 512 + j];
        float gi = g_XWB1L[b * 1024 + j];
        float gg = g_XWB1L[b * 1024 + 512 + j];
        float go = g_XWB1L[b * 1024 + 768 + j];
        float c = sigf(gi) * tanhf_fast(gg);   // c0 = 0 -> f*c0 vanishes
        last[256 + j] = sigf(go) * tanhf_fast(c);
    }
    __syncthreads();
    float acc = fc_b[tid];
    const float4* w  = (const float4*)&fc_w[(size_t)tid * 512];
    const float4* l4 = (const float4*)last;
#pragma unroll 8
    for (int k = 0; k < 128; ++k) {
        float4 ww = w[k]; float4 ll = l4[k];
        acc += ww.x * ll.x + ww.y * ll.y + ww.z * ll.z + ww.w * ll.w;
    }
    outp[b * 128 + tid] = acc;
}

// ---------------- launch ------------------------------------------------------
extern "C" void kernel_launch(void* const* d_in, const int* in_sizes, int n_in,
                              void* d_out, int out_size)
{
    const float* x     = (const float*)d_in[0];
    const float* wih0f = (const float*)d_in[1];
    const float* whh0f = (const float*)d_in[2];
    const float* b0f   = (const float*)d_in[3];
    const float* wih0b = (const float*)d_in[4];
    const float* whh0b = (const float*)d_in[5];
    const float* b0b   = (const float*)d_in[6];
    const float* wih1f = (const float*)d_in[7];
    const float* whh1f = (const float*)d_in[8];
    const float* b1f   = (const float*)d_in[9];
    const float* wih1b = (const float*)d_in[10];
    const float* whh1b = (const float*)d_in[11];
    const float* b1b   = (const float*)d_in[12];
    const float* fcw   = (const float*)d_in[13];
    const float* fcb   = (const float*)d_in[14];
    float* outp = (float*)d_out;

    float *A0, *XWA, *XWB, *OUT0, *LAST, *XWB1L;
    cudaGetSymbolAddress((void**)&A0,    g_A0);
    cudaGetSymbolAddress((void**)&XWA,   g_XWA);
    cudaGetSymbolAddress((void**)&XWB,   g_XWB);
    cudaGetSymbolAddress((void**)&OUT0,  g_OUT0);
    cudaGetSymbolAddress((void**)&LAST,  g_LAST);
    cudaGetSymbolAddress((void**)&XWB1L, g_XWB1L);

    // 1) transpose x -> A0
    {
        dim3 tb(32, 8);
        dim3 tg(T_STEPS / 32, INF / 32, BATCH);
        transpose_x<<<tg, tb>>>(x, A0);
    }
    // 2) layer-0 input projections (both directions)
    {
        dim3 gb(1024 / 128, (T_STEPS * BATCH) / 128);
        gemm_bias<<<gb, 256>>>(A0, wih0f, b0f, XWA, T_STEPS * BATCH, 1024, INF);
        gemm_bias<<<gb, 256>>>(A0, wih0b, b0b, XWB, T_STEPS * BATCH, 1024, INF);
    }
    // 3) layer-0 bidirectional recurrence -> OUT0
    rec_kernel<0><<<128, 256>>>(XWA, XWB, whh0f, whh0b, OUT0);
    // 4) layer-1 fwd input projection (reuse XWA)
    {
        dim3 gb(1024 / 128, (T_STEPS * BATCH) / 128);
        gemm_bias<<<gb, 256>>>(OUT0, wih1f, b1f, XWA, T_STEPS * BATCH, 1024, 512);
    }
    // 5) layer-1 fwd recurrence -> g_LAST cols 0:256
    rec_kernel<1><<<128, 256>>>(XWA, XWA, whh1f, whh1f, LAST);
    // 6) layer-1 bwd needs only its FIRST step (t = T-1): one 32-row GEMM
    {
        dim3 gs(1024 / 128, 1);
        gemm_bias<<<gs, 256>>>(OUT0 + (size_t)(T_STEPS - 1) * BATCH * 512,
                               wih1b, b1b, XWB1L, BATCH, 1024, 512);
    }
    // 7) hb1 elementwise + FC
    final_kernel<<<BATCH, 128>>>(fcw, fcb, outp);
}

// round 4
// speedup vs baseline: 1.5373x; 1.3403x over previous
#include <cuda_runtime.h>
#include <math.h>
#include <cstdint>

#define T_STEPS 2048
#define BATCH 32
#define INF 128
#define HID 256

typedef unsigned long long ull;

// ---------------- scratch ------------------------------------------------------
__device__ float g_A0[(size_t)T_STEPS * BATCH * INF];
__device__ float g_XWA[(size_t)T_STEPS * BATCH * 1024];
__device__ float g_XWB[(size_t)T_STEPS * BATCH * 1024];
__device__ float g_OUT0[(size_t)T_STEPS * BATCH * 512];
__device__ float g_LAST[BATCH * 512];
__device__ float g_XWB1L[BATCH * 1024];

__device__ __forceinline__ float sigf(float x) {
    return __fdividef(1.0f, 1.0f + __expf(-x));
}
__device__ __forceinline__ float tanhf_fast(float x) {
    float e = __expf(2.0f * x);
    return 1.0f - __fdividef(2.0f, e + 1.0f);
}
__device__ __forceinline__ uint32_t smem_u32(const void* p) {
    uint32_t a;
    asm("{ .reg .u64 t; cvta.to.shared.u64 t, %1; cvt.u32.u64 %0, t; }" : "=r"(a) : "l"(p));
    return a;
}
__device__ __forceinline__ void fma2(ull& d, ull a, ull b) {
    asm("fma.rn.f32x2 %0, %1, %2, %0;" : "+l"(d) : "l"(a), "l"(b));
}
__device__ __forceinline__ float2 unpack2(ull v) {
    float2 f; asm("mov.b64 {%0, %1}, %2;" : "=f"(f.x), "=f"(f.y) : "l"(v)); return f;
}
__device__ __forceinline__ void mbar_wait_cluster(uint32_t addr, unsigned phase) {
    asm volatile(
        "{\n\t.reg .pred P;\n\t"
        "WAIT_%=:\n\t"
        "mbarrier.try_wait.parity.acquire.cluster.shared::cta.b64 P, [%0], %1, 0x989680;\n\t"
        "@P bra.uni DONE_%=;\n\t"
        "bra.uni WAIT_%=;\n\t"
        "DONE_%=:\n\t}"
        :: "r"(addr), "r"(phase) : "memory");
}

// ---------------- transpose x[B,1,IN,T] -> A0[(t*B+b), f] ------------------------
__global__ void transpose_x(const float* __restrict__ x, float* __restrict__ A0) {
    __shared__ float tile[32][33];
    int b = blockIdx.z;
    int f0 = blockIdx.y * 32, t0 = blockIdx.x * 32;
    int tx = threadIdx.x, ty = threadIdx.y;
#pragma unroll
    for (int i = 0; i < 32; i += 8)
        tile[ty + i][tx] = x[((size_t)b * INF + (f0 + ty + i)) * T_STEPS + t0 + tx];
    __syncthreads();
#pragma unroll
    for (int i = 0; i < 32; i += 8)
        A0[(((size_t)(t0 + ty + i)) * BATCH + b) * INF + f0 + tx] = tile[tx][ty + i];
}

// ---------------- fp32 GEMM (double-buffered): C = A * W^T + bias ---------------
__global__ void __launch_bounds__(256) gemm_bias(
    const float* __restrict__ A, const float* __restrict__ W,
    const float* __restrict__ bias, float* __restrict__ C,
    int M, int N, int K)
{
    __shared__ float As[2][16][132];
    __shared__ float Bs[2][16][132];
    const int bn = blockIdx.x * 128;
    const int bm = blockIdx.y * 128;
    const int tid = threadIdx.x;
    const int tx = tid & 15, ty = tid >> 4;
    const int lrow = tid >> 2;
    const int lk = (tid & 3) << 2;

    float4 va[2], vw[2];
#pragma unroll
    for (int h = 0; h < 2; ++h) {
        int m = bm + lrow + h * 64;
        va[h] = (m < M) ? *(const float4*)&A[(size_t)m * K + lk]
                        : make_float4(0.f, 0.f, 0.f, 0.f);
        vw[h] = *(const float4*)&W[(size_t)(bn + lrow + h * 64) * K + lk];
    }
    int buf = 0;
#pragma unroll
    for (int h = 0; h < 2; ++h) {
        As[buf][lk + 0][lrow + h * 64] = va[h].x; As[buf][lk + 1][lrow + h * 64] = va[h].y;
        As[buf][lk + 2][lrow + h * 64] = va[h].z; As[buf][lk + 3][lrow + h * 64] = va[h].w;
        Bs[buf][lk + 0][lrow + h * 64] = vw[h].x; Bs[buf][lk + 1][lrow + h * 64] = vw[h].y;
        Bs[buf][lk + 2][lrow + h * 64] = vw[h].z; Bs[buf][lk + 3][lrow + h * 64] = vw[h].w;
    }
    __syncthreads();

    float acc[8][8];
#pragma unroll
    for (int i = 0; i < 8; i++)
#pragma unroll
        for (int j = 0; j < 8; j++) acc[i][j] = 0.f;

    for (int k0 = 16; k0 <= K; k0 += 16) {
        const bool more = (k0 < K);
        if (more) {
#pragma unroll
            for (int h = 0; h < 2; ++h) {
                int m = bm + lrow + h * 64;
                va[h] = (m < M) ? *(const float4*)&A[(size_t)m * K + k0 + lk]
                                : make_float4(0.f, 0.f, 0.f, 0.f);
                vw[h] = *(const float4*)&W[(size_t)(bn + lrow + h * 64) * K + k0 + lk];
            }
        }
#pragma unroll
        for (int k = 0; k < 16; ++k) {
            float a[8], bb[8];
            *(float4*)&a[0]  = *(const float4*)&As[buf][k][ty * 8];
            *(float4*)&a[4]  = *(const float4*)&As[buf][k][ty * 8 + 4];
            *(float4*)&bb[0] = *(const float4*)&Bs[buf][k][tx * 8];
            *(float4*)&bb[4] = *(const float4*)&Bs[buf][k][tx * 8 + 4];
#pragma unroll
            for (int i = 0; i < 8; i++)
#pragma unroll
                for (int j = 0; j < 8; j++) acc[i][j] += a[i] * bb[j];
        }
        if (more) {
            int nb = buf ^ 1;
#pragma unroll
            for (int h = 0; h < 2; ++h) {
                As[nb][lk + 0][lrow + h * 64] = va[h].x; As[nb][lk + 1][lrow + h * 64] = va[h].y;
                As[nb][lk + 2][lrow + h * 64] = va[h].z; As[nb][lk + 3][lrow + h * 64] = va[h].w;
                Bs[nb][lk + 0][lrow + h * 64] = vw[h].x; Bs[nb][lk + 1][lrow + h * 64] = vw[h].y;
                Bs[nb][lk + 2][lrow + h * 64] = vw[h].z; Bs[nb][lk + 3][lrow + h * 64] = vw[h].w;
            }
            __syncthreads();
            buf = nb;
        }
    }
#pragma unroll
    for (int i = 0; i < 8; i++) {
        int row = bm + ty * 8 + i;
        if (row >= M) continue;
#pragma unroll
        for (int j = 0; j < 8; j += 4) {
            int col = bn + tx * 8 + j;
            float4 o;
            o.x = acc[i][j + 0] + bias[col + 0];
            o.y = acc[i][j + 1] + bias[col + 1];
            o.z = acc[i][j + 2] + bias[col + 2];
            o.w = acc[i][j + 3] + bias[col + 3];
            *(float4*)&C[(size_t)row * N + col] = o;
        }
    }
}

// ---------------- cluster-based persistent recurrence ----------------------------
// 16 clusters x 8 CTAs. CTA rank = 32-unit hidden chunk. Each thread: 2 gate rows
// x one k-quarter (64 k) x NB batches. x2 lanes run along K (consecutive W values
// form natural register pairs -> no packing MOVs). Exchange: 256 remote stores,
// sync, then ONE release-arrive per peer (barrier count = 8).
template <int LAYER>
__global__ void __cluster_dims__(8, 1, 1) __launch_bounds__(256, 1) rec_kernel(
    const float* __restrict__ xwF, const float* __restrict__ xwB,
    const float* __restrict__ whhF, const float* __restrict__ whhB,
    float* __restrict__ out)
{
    constexpr int NB    = (LAYER == 0) ? 4 : 2;   // batches per cluster
    constexpr int CELLS = NB * 32;
    constexpr int F4PP  = NB * 8;                 // float4s per peer
    constexpr int STOR  = 8 * F4PP;               // storer threads (256 / 128)

    __shared__ alignas(16) float hp[2][NB][256];  // [parity][batch][k]
    __shared__ float gpart[4][NB][128];           // [quarter][batch][gate-row]
    __shared__ alignas(16) float stage[NB][32];
    __shared__ alignas(8) unsigned long long mbar[2];

    const int tid  = threadIdx.x;
    const unsigned rank = blockIdx.x & 7;
    const unsigned cl   = blockIdx.x >> 3;

    int dir, b0;
    if (LAYER == 0) { dir = cl >> 3; b0 = (cl & 7) * NB; }
    else            { dir = 0;       b0 = cl * NB; }
    const int j0 = rank * 32;

    const float* xw  = dir ? xwB  : xwF;
    const float* whh = dir ? whhB : whhF;

    const int q  = tid >> 6;       // k-quarter (warp-uniform)
    const int rg = tid & 63;       // row group
    const int rA = rg, rB = rg + 64;
    const int grA = ((rA >> 5) << 8) + j0 + (rA & 31);
    const int grB = ((rB >> 5) << 8) + j0 + (rB & 31);

    // W rows -> registers as natural k-pairs (ull = 2 consecutive fp32 along K)
    ull wA[32], wB[32];
    {
        const ulonglong2* ra = (const ulonglong2*)&whh[(size_t)grA * 256 + q * 64];
        const ulonglong2* rb = (const ulonglong2*)&whh[(size_t)grB * 256 + q * 64];
#pragma unroll
        for (int i = 0; i < 16; ++i) {
            ulonglong2 x = ra[i]; wA[2 * i] = x.x; wA[2 * i + 1] = x.y;
            ulonglong2 y = rb[i]; wB[2 * i] = y.x; wB[2 * i + 1] = y.y;
        }
    }

    for (int idx = tid; idx < 2 * NB * 256; idx += 256) ((float*)hp)[idx] = 0.f;
    if (tid == 0) {
        asm volatile("mbarrier.init.shared.b64 [%0], %1;" :: "r"(smem_u32(&mbar[0])), "r"(8));
        asm volatile("mbarrier.init.shared.b64 [%0], %1;" :: "r"(smem_u32(&mbar[1])), "r"(8));
    }
    __syncthreads();
    asm volatile("barrier.cluster.arrive.aligned;" ::: "memory");
    asm volatile("barrier.cluster.wait.aligned;" ::: "memory");

    const int cb = tid >> 5, cj = tid & 31;
    float c_state = 0.f;
    unsigned ph0 = 0, ph1 = 0;
    const uint32_t mb0 = smem_u32(&mbar[0]), mb1 = smem_u32(&mbar[1]);

    for (int t = 0; t < T_STEPS; ++t) {
        const int tr = dir ? (T_STEPS - 1 - t) : t;
        const int p = t & 1;

        // prefetch xw gates for this step (hidden behind wait + matvec)
        float xg0 = 0.f, xg1 = 0.f, xg2 = 0.f, xg3 = 0.f;
        if (tid < CELLS) {
            size_t base = ((size_t)tr * BATCH + b0 + cb) * 1024 + j0 + cj;
            xg0 = __ldcs(&xw[base]);
            xg1 = __ldcs(&xw[base + 256]);
            xg2 = __ldcs(&xw[base + 512]);
            xg3 = __ldcs(&xw[base + 768]);
        }

        if (t > 0) {
            if (p) { mbar_wait_cluster(mb1, ph1); ph1 ^= 1; }
            else   { mbar_wait_cluster(mb0, ph0); ph0 ^= 1; }
        }

        // ---- matvec: acc lanes = (k even, k odd); h loads broadcast, k-contiguous
        ull accA[NB], accB[NB];
#pragma unroll
        for (int b = 0; b < NB; ++b) { accA[b] = 0ull; accB[b] = 0ull; }
        const float* hbase = &hp[p][0][q * 64];
#pragma unroll
        for (int i = 0; i < 16; ++i) {
#pragma unroll
            for (int b = 0; b < NB; ++b) {
                ulonglong2 hv = *(const ulonglong2*)(hbase + b * 256 + 4 * i);
                fma2(accA[b], wA[2 * i],     hv.x);
                fma2(accA[b], wA[2 * i + 1], hv.y);
                fma2(accB[b], wB[2 * i],     hv.x);
                fma2(accB[b], wB[2 * i + 1], hv.y);
            }
        }
#pragma unroll
        for (int b = 0; b < NB; ++b) {
            float2 a = unpack2(accA[b]); gpart[q][b][rA] = a.x + a.y;
            float2 c = unpack2(accB[b]); gpart[q][b][rB] = c.x + c.y;
        }
        __syncthreads();

        // ---- cell update
        if (tid < CELLS) {
            float gi = xg0 + gpart[0][cb][cj]      + gpart[1][cb][cj]      + gpart[2][cb][cj]      + gpart[3][cb][cj];
            float gf = xg1 + gpart[0][cb][32 + cj] + gpart[1][cb][32 + cj] + gpart[2][cb][32 + cj] + gpart[3][cb][32 + cj];
            float gg = xg2 + gpart[0][cb][64 + cj] + gpart[1][cb][64 + cj] + gpart[2][cb][64 + cj] + gpart[3][cb][64 + cj];
            float go = xg3 + gpart[0][cb][96 + cj] + gpart[1][cb][96 + cj] + gpart[2][cb][96 + cj] + gpart[3][cb][96 + cj];
            float ii = sigf(gi), ff = sigf(gf), oo = sigf(go);
            c_state = ff * c_state + ii * tanhf_fast(gg);
            float h = oo * tanhf_fast(c_state);
            stage[cb][cj] = h;
            if (LAYER == 0)
                out[((size_t)tr * BATCH + (b0 + cb)) * 512 + (dir << 8) + j0 + cj] = h;
            else if (t == T_STEPS - 1)
                out[(b0 + cb) * 512 + j0 + cj] = h;
        }
        if (t == T_STEPS - 1) break;
        __syncthreads();

        // ---- remote scatter of our 32-unit h chunk to all 8 cluster CTAs ----
        if (STOR == 256 || tid < STOR) {
            const int peer = tid / F4PP;
            const int i    = tid % F4PP;
            float4 val = ((const float4*)stage)[i];
            const int b  = i >> 3;
            const int jj = (i & 7) * 4;
            uint32_t laddr = smem_u32(&hp[p ^ 1][b][j0 + jj]);
            uint32_t raddr;
            asm("mapa.shared::cluster.u32 %0, %1, %2;" : "=r"(raddr) : "r"(laddr), "r"(peer));
            asm volatile("st.shared::cluster.v4.f32 [%0], {%1, %2, %3, %4};"
                         :: "r"(raddr), "f"(val.x), "f"(val.y), "f"(val.z), "f"(val.w)
                         : "memory");
        }
        __syncthreads();
        // ---- ONE release-arrive per peer (count=8 at each barrier) ----
        if (tid < 8) {
            uint32_t lmb = p ? mb0 : mb1;     // barrier of next buffer
            uint32_t rmb;
            asm("mapa.shared::cluster.u32 %0, %1, %2;" : "=r"(rmb) : "r"(lmb), "r"(tid));
            asm volatile("mbarrier.arrive.release.cluster.shared::cluster.b64 _, [%0];"
                         :: "r"(rmb) : "memory");
        }
    }
}

// ---------------- final: hb1(T-1) one-step + FC -------------------------------
__global__ void final_kernel(const float* __restrict__ fc_w, const float* __restrict__ fc_b,
                             float* __restrict__ outp)
{
    __shared__ float last[512];
    int b = blockIdx.x, tid = threadIdx.x;   // 128 threads
    for (int j = tid; j < 256; j += 128) {
        last[j] = g_LAST[b * 512 + j];
        float gi = g_XWB1L[b * 1024 + j];
        float gg = g_XWB1L[b * 1024 + 512 + j];
        float go = g_XWB1L[b * 1024 + 768 + j];
        float c = sigf(gi) * tanhf_fast(gg);   // c0 = 0 -> f*c0 vanishes
        last[256 + j] = sigf(go) * tanhf_fast(c);
    }
    __syncthreads();
    float acc = fc_b[tid];
    const float4* w  = (const float4*)&fc_w[(size_t)tid * 512];
    const float4* l4 = (const float4*)last;
#pragma unroll 8
    for (int k = 0; k < 128; ++k) {
        float4 ww = w[k]; float4 ll = l4[k];
        acc += ww.x * ll.x + ww.y * ll.y + ww.z * ll.z + ww.w * ll.w;
    }
    outp[b * 128 + tid] = acc;
}

// ---------------- launch ------------------------------------------------------
extern "C" void kernel_launch(void* const* d_in, const int* in_sizes, int n_in,
                              void* d_out, int out_size)
{
    const float* x     = (const float*)d_in[0];
    const float* wih0f = (const float*)d_in[1];
    const float* whh0f = (const float*)d_in[2];
    const float* b0f   = (const float*)d_in[3];
    const float* wih0b = (const float*)d_in[4];
    const float* whh0b = (const float*)d_in[5];
    const float* b0b   = (const float*)d_in[6];
    const float* wih1f = (const float*)d_in[7];
    const float* whh1f = (const float*)d_in[8];
    const float* b1f   = (const float*)d_in[9];
    const float* wih1b = (const float*)d_in[10];
    const float* whh1b = (const float*)d_in[11];
    const float* b1b   = (const float*)d_in[12];
    const float* fcw   = (const float*)d_in[13];
    const float* fcb   = (const float*)d_in[14];
    float* outp = (float*)d_out;

    float *A0, *XWA, *XWB, *OUT0, *LAST, *XWB1L;
    cudaGetSymbolAddress((void**)&A0,    g_A0);
    cudaGetSymbolAddress((void**)&XWA,   g_XWA);
    cudaGetSymbolAddress((void**)&XWB,   g_XWB);
    cudaGetSymbolAddress((void**)&OUT0,  g_OUT0);
    cudaGetSymbolAddress((void**)&LAST,  g_LAST);
    cudaGetSymbolAddress((void**)&XWB1L, g_XWB1L);

    // 1) transpose x -> A0
    {
        dim3 tb(32, 8);
        dim3 tg(T_STEPS / 32, INF / 32, BATCH);
        transpose_x<<<tg, tb>>>(x, A0);
    }
    // 2) layer-0 input projections (both directions)
    {
        dim3 gb(1024 / 128, (T_STEPS * BATCH) / 128);
        gemm_bias<<<gb, 256>>>(A0, wih0f, b0f, XWA, T_STEPS * BATCH, 1024, INF);
        gemm_bias<<<gb, 256>>>(A0, wih0b, b0b, XWB, T_STEPS * BATCH, 1024, INF);
    }
    // 3) layer-0 bidirectional recurrence -> OUT0
    rec_kernel<0><<<128, 256>>>(XWA, XWB, whh0f, whh0b, OUT0);
    // 4) layer-1 fwd input projection (reuse XWA)
    {
        dim3 gb(1024 / 128, (T_STEPS * BATCH) / 128);
        gemm_bias<<<gb, 256>>>(OUT0, wih1f, b1f, XWA, T_STEPS * BATCH, 1024, 512);
    }
    // 5) layer-1 fwd recurrence -> g_LAST cols 0:256
    rec_kernel<1><<<128, 256>>>(XWA, XWA, whh1f, whh1f, LAST);
    // 6) layer-1 bwd needs only its FIRST step (t = T-1): one 32-row GEMM
    {
        dim3 gs(1024 / 128, 1);
        gemm_bias<<<gs, 256>>>(OUT0 + (size_t)(T_STEPS - 1) * BATCH * 512,
                               wih1b, b1b, XWB1L, BATCH, 1024, 512);
    }
    // 7) hb1 elementwise + FC
    final_kernel<<<BATCH, 128>>>(fcw, fcb, outp);
}

// round 6
// speedup vs baseline: 1.6859x; 1.0967x over previous
#include <cuda_runtime.h>
#include <cuda_bf16.h>
#include <math.h>
#include <cstdint>

#define T_STEPS 2048
#define BATCH 32
#define INF 128
#define HID 256

typedef unsigned long long ull;
typedef __nv_bfloat16 bf16;

// ---------------- scratch ------------------------------------------------------
__device__ float g_XWA[(size_t)T_STEPS * BATCH * 1024];
__device__ float g_XWB[(size_t)T_STEPS * BATCH * 1024];
__device__ float g_OUT0[(size_t)T_STEPS * BATCH * 512];
__device__ float g_LAST[BATCH * 512];
__device__ float g_XWB1L[BATCH * 1024];
// bf16 hi/lo planes
__device__ bf16 g_A0H[(size_t)T_STEPS * BATCH * INF];
__device__ bf16 g_A0L[(size_t)T_STEPS * BATCH * INF];
__device__ bf16 g_O0H[(size_t)T_STEPS * BATCH * 512];
__device__ bf16 g_O0L[(size_t)T_STEPS * BATCH * 512];
__device__ bf16 g_W0FH[1024 * 128], g_W0FL[1024 * 128];
__device__ bf16 g_W0BH[1024 * 128], g_W0BL[1024 * 128];
__device__ bf16 g_W1FH[1024 * 512], g_W1FL[1024 * 512];

__device__ __forceinline__ float sigf(float x) {
    return __fdividef(1.0f, 1.0f + __expf(-x));
}
__device__ __forceinline__ float tanhf_fast(float x) {
    float e = __expf(2.0f * x);
    return 1.0f - __fdividef(2.0f, e + 1.0f);
}
__device__ __forceinline__ uint32_t smem_u32(const void* p) {
    uint32_t a;
    asm("{ .reg .u64 t; cvta.to.shared.u64 t, %1; cvt.u32.u64 %0, t; }" : "=r"(a) : "l"(p));
    return a;
}
__device__ __forceinline__ void fma2(ull& d, ull a, ull b) {
    asm("fma.rn.f32x2 %0, %1, %2, %0;" : "+l"(d) : "l"(a), "l"(b));
}
__device__ __forceinline__ float2 unpack2(ull v) {
    float2 f; asm("mov.b64 {%0, %1}, %2;" : "=f"(f.x), "=f"(f.y) : "l"(v)); return f;
}
__device__ __forceinline__ void mbar_wait_cluster(uint32_t addr, unsigned phase) {
    asm volatile(
        "{\n\t.reg .pred P;\n\t"
        "WAIT_%=:\n\t"
        "mbarrier.try_wait.parity.acquire.cluster.shared::cta.b64 P, [%0], %1, 0x989680;\n\t"
        "@P bra.uni DONE_%=;\n\t"
        "bra.uni WAIT_%=;\n\t"
        "DONE_%=:\n\t}"
        :: "r"(addr), "r"(phase) : "memory");
}
__device__ __forceinline__ void cp16(uint32_t saddr, const void* gaddr) {
    asm volatile("cp.async.cg.shared.global [%0], [%1], 16;" :: "r"(saddr), "l"(gaddr));
}
__device__ __forceinline__ void ldsm4(uint32_t* r, uint32_t addr) {
    asm volatile("ldmatrix.sync.aligned.m8n8.x4.shared.b16 {%0,%1,%2,%3}, [%4];"
                 : "=r"(r[0]), "=r"(r[1]), "=r"(r[2]), "=r"(r[3]) : "r"(addr));
}
__device__ __forceinline__ void mma_bf16(float* d, const uint32_t* a, const uint32_t* b) {
    asm volatile(
        "mma.sync.aligned.m16n8k16.row.col.f32.bf16.bf16.f32 "
        "{%0,%1,%2,%3}, {%4,%5,%6,%7}, {%8,%9}, {%0,%1,%2,%3};"
        : "+f"(d[0]), "+f"(d[1]), "+f"(d[2]), "+f"(d[3])
        : "r"(a[0]), "r"(a[1]), "r"(a[2]), "r"(a[3]), "r"(b[0]), "r"(b[1]));
}
__device__ __forceinline__ void split1(float v, bf16& h, bf16& l) {
    h = __float2bfloat16(v);
    l = __float2bfloat16(v - __bfloat162float(h));
}

// ---------------- transpose x[B,1,IN,T] -> A0 hi/lo [(t*B+b), f] -----------------
__global__ void transpose_x(const float* __restrict__ x,
                            bf16* __restrict__ A0h, bf16* __restrict__ A0l) {
    __shared__ float tile[32][33];
    int b = blockIdx.z;
    int f0 = blockIdx.y * 32, t0 = blockIdx.x * 32;
    int tx = threadIdx.x, ty = threadIdx.y;
#pragma unroll
    for (int i = 0; i < 32; i += 8)
        tile[ty + i][tx] = x[((size_t)b * INF + (f0 + ty + i)) * T_STEPS + t0 + tx];
    __syncthreads();
#pragma unroll
    for (int i = 0; i < 32; i += 8) {
        float v = tile[tx][ty + i];
        size_t idx = (((size_t)(t0 + ty + i)) * BATCH + b) * INF + f0 + tx;
        bf16 h, l; split1(v, h, l);
        A0h[idx] = h; A0l[idx] = l;
    }
}

// ---------------- split f32 -> bf16 hi/lo --------------------------------------
__global__ void split_bf16(const float* __restrict__ in, bf16* __restrict__ hi,
                           bf16* __restrict__ lo, int n) {
    int i = blockIdx.x * blockDim.x + threadIdx.x;
    if (i < n) { bf16 h, l; split1(in[i], h, l); hi[i] = h; lo[i] = l; }
}

// ---------------- HMMA split-bf16 GEMM: C = A(f32~hi+lo) * W^T + bias ----------
// Tile 128M x 128N, 8 warps (2x4), warp tile 64x32, K staged 32, cp.async pipelined.
__global__ void __launch_bounds__(256) gemm_mma(
    const bf16* __restrict__ Ah, const bf16* __restrict__ Al,
    const bf16* __restrict__ Wh, const bf16* __restrict__ Wl,
    const float* __restrict__ bias, float* __restrict__ C,
    int K, int N_total)
{
    extern __shared__ char sraw[];
    const uint32_t base = (smem_u32(sraw) + 127u) & ~127u;
    // A planes: [buf][plane] 128 rows x 80B; B likewise
    const uint32_t As = base;
    const uint32_t Bs = base + 40960u;

    const int tid = threadIdx.x;
    const int lane = tid & 31, wid = tid >> 5;
    const int wm = wid & 1, wn = wid >> 1;
    const int bm = blockIdx.y * 128, bn = blockIdx.x * 128;

    // per-lane ldmatrix offsets
    const int a_ro = ((lane >> 3) & 1) * 8 + (lane & 7);
    const int a_co = (lane >> 4) * 16;                 // bytes
    const int b_ro = ((lane >> 4) << 3) + (lane & 7);
    const int b_co = ((lane >> 3) & 1) * 16;           // bytes

    // cp.async chunk mapping: c = tid*2 + h -> row = c>>2, blk = c&3
    const int c0 = tid * 2;

    float acc[4][4][4];
#pragma unroll
    for (int mt = 0; mt < 4; ++mt)
#pragma unroll
        for (int nt = 0; nt < 4; ++nt)
#pragma unroll
            for (int e = 0; e < 4; ++e) acc[mt][nt][e] = 0.f;

    const int nst = K >> 5;
    int buf = 0;

    // issue stage 0
#pragma unroll
    for (int h = 0; h < 2; ++h) {
        int c = c0 + h, row = c >> 2, blk = c & 3;
        size_t ga = (size_t)(bm + row) * K + blk * 8;
        size_t gw = (size_t)(bn + row) * K + blk * 8;
        uint32_t so = (uint32_t)(row * 80 + blk * 16);
        cp16(As + so,          Ah + ga);
        cp16(As + 10240u + so, Al + ga);
        cp16(Bs + so,          Wh + gw);
        cp16(Bs + 10240u + so, Wl + gw);
    }
    asm volatile("cp.async.commit_group;");

    for (int st = 0; st < nst; ++st) {
        if (st + 1 < nst) {
            const int nb = buf ^ 1;
            const int k0 = (st + 1) * 32;
#pragma unroll
            for (int h = 0; h < 2; ++h) {
                int c = c0 + h, row = c >> 2, blk = c & 3;
                size_t ga = (size_t)(bm + row) * K + k0 + blk * 8;
                size_t gw = (size_t)(bn + row) * K + k0 + blk * 8;
                uint32_t so = (uint32_t)(nb * 20480 + row * 80 + blk * 16);
                cp16(As + so,          Ah + ga);
                cp16(As + 10240u + so, Al + ga);
                cp16(Bs + so,          Wh + gw);
                cp16(Bs + 10240u + so, Wl + gw);
            }
            asm volatile("cp.async.commit_group;");
            asm volatile("cp.async.wait_group 1;");
        } else {
            asm volatile("cp.async.wait_group 0;");
        }
        __syncthreads();

        const uint32_t Ab = As + buf * 20480u;
        const uint32_t Bb = Bs + buf * 20480u;
#pragma unroll
        for (int ks = 0; ks < 2; ++ks) {
            const uint32_t kb = ks * 32u;    // bytes
            uint32_t bh[2][4], bl[2][4];
#pragma unroll
            for (int pr = 0; pr < 2; ++pr) {
                uint32_t ro = (uint32_t)((wn * 32 + pr * 16 + b_ro) * 80) + kb + b_co;
                ldsm4(bh[pr], Bb + ro);
                ldsm4(bl[pr], Bb + 10240u + ro);
            }
#pragma unroll
            for (int mt = 0; mt < 4; ++mt) {
                uint32_t ah[4], al[4];
                uint32_t ro = (uint32_t)((wm * 64 + mt * 16 + a_ro) * 80) + kb + a_co;
                ldsm4(ah, Ab + ro);
                ldsm4(al, Ab + 10240u + ro);
#pragma unroll
                for (int nt = 0; nt < 4; ++nt) {
                    const uint32_t* bfh = &bh[nt >> 1][(nt & 1) * 2];
                    const uint32_t* bfl = &bl[nt >> 1][(nt & 1) * 2];
                    mma_bf16(acc[mt][nt], ah, bfh);
                    mma_bf16(acc[mt][nt], al, bfh);
                    mma_bf16(acc[mt][nt], ah, bfl);
                }
            }
        }
        __syncthreads();
        buf ^= 1;
    }

    // epilogue
    const int g = lane >> 2, tg = lane & 3;
#pragma unroll
    for (int nt = 0; nt < 4; ++nt) {
        const int col = bn + wn * 32 + nt * 8 + tg * 2;
        const float b0 = bias[col], b1 = bias[col + 1];
#pragma unroll
        for (int mt = 0; mt < 4; ++mt) {
            const int row = bm + wm * 64 + mt * 16 + g;
            float2 v0 = make_float2(acc[mt][nt][0] + b0, acc[mt][nt][1] + b1);
            float2 v1 = make_float2(acc[mt][nt][2] + b0, acc[mt][nt][3] + b1);
            *(float2*)&C[(size_t)row * N_total + col] = v0;
            *(float2*)&C[(size_t)(row + 8) * N_total + col] = v1;
        }
    }
}

// ---------------- small SIMT GEMM (32-row layer1-bwd projection) ----------------
__global__ void __launch_bounds__(256) gemm_bias(
    const float* __restrict__ A, const float* __restrict__ W,
    const float* __restrict__ bias, float* __restrict__ C,
    int M, int N, int K)
{
    __shared__ float As[16][132];
    __shared__ float Bs[16][132];
    const int bn = blockIdx.x * 128;
    const int bm = blockIdx.y * 128;
    const int tid = threadIdx.x;
    const int tx = tid & 15, ty = tid >> 4;
    const int lrow = tid >> 2;
    const int lk = (tid & 3) << 2;

    float acc[8][8];
#pragma unroll
    for (int i = 0; i < 8; i++)
#pragma unroll
        for (int j = 0; j < 8; j++) acc[i][j] = 0.f;

    for (int k0 = 0; k0 < K; k0 += 16) {
#pragma unroll
        for (int h = 0; h < 2; ++h) {
            int m = bm + lrow + h * 64;
            float4 v = (m < M) ? *(const float4*)&A[(size_t)m * K + k0 + lk]
                               : make_float4(0.f, 0.f, 0.f, 0.f);
            As[lk + 0][lrow + h * 64] = v.x; As[lk + 1][lrow + h * 64] = v.y;
            As[lk + 2][lrow + h * 64] = v.z; As[lk + 3][lrow + h * 64] = v.w;
            int n = bn + lrow + h * 64;
            float4 wv = *(const float4*)&W[(size_t)n * K + lk + k0];
            Bs[lk + 0][lrow + h * 64] = wv.x; Bs[lk + 1][lrow + h * 64] = wv.y;
            Bs[lk + 2][lrow + h * 64] = wv.z; Bs[lk + 3][lrow + h * 64] = wv.w;
        }
        __syncthreads();
#pragma unroll
        for (int k = 0; k < 16; ++k) {
            float a[8], bb[8];
            *(float4*)&a[0]  = *(const float4*)&As[k][ty * 8];
            *(float4*)&a[4]  = *(const float4*)&As[k][ty * 8 + 4];
            *(float4*)&bb[0] = *(const float4*)&Bs[k][tx * 8];
            *(float4*)&bb[4] = *(const float4*)&Bs[k][tx * 8 + 4];
#pragma unroll
            for (int i = 0; i < 8; i++)
#pragma unroll
                for (int j = 0; j < 8; j++) acc[i][j] += a[i] * bb[j];
        }
        __syncthreads();
    }
#pragma unroll
    for (int i = 0; i < 8; i++) {
        int row = bm + ty * 8 + i;
        if (row >= M) continue;
#pragma unroll
        for (int j = 0; j < 8; j += 4) {
            int col = bn + tx * 8 + j;
            float4 o;
            o.x = acc[i][j + 0] + bias[col + 0];
            o.y = acc[i][j + 1] + bias[col + 1];
            o.z = acc[i][j + 2] + bias[col + 2];
            o.w = acc[i][j + 3] + bias[col + 3];
            *(float4*)&C[(size_t)row * N + col] = o;
        }
    }
}

// ---------------- cluster-based persistent recurrence ----------------------------
template <int LAYER>
__global__ void __cluster_dims__(8, 1, 1) __launch_bounds__(256, 1) rec_kernel(
    const float* __restrict__ xwF, const float* __restrict__ xwB,
    const float* __restrict__ whhF, const float* __restrict__ whhB,
    float* __restrict__ out, bf16* __restrict__ outh, bf16* __restrict__ outl)
{
    constexpr int NB    = (LAYER == 0) ? 4 : 2;
    constexpr int CELLS = NB * 32;
    constexpr int F4PP  = NB * 8;
    constexpr int STOR  = 8 * F4PP;

    __shared__ alignas(16) float hp[2][NB][256];
    __shared__ float gpart[4][NB][128];
    __shared__ alignas(16) float stage[NB][32];
    __shared__ alignas(8) unsigned long long mbar[2];

    const int tid  = threadIdx.x;
    const unsigned rank = blockIdx.x & 7;
    const unsigned cl   = blockIdx.x >> 3;

    int dir, b0;
    if (LAYER == 0) { dir = cl >> 3; b0 = (cl & 7) * NB; }
    else            { dir = 0;       b0 = cl * NB; }
    const int j0 = rank * 32;

    const float* xw  = dir ? xwB  : xwF;
    const float* whh = dir ? whhB : whhF;

    const int q  = tid >> 6;
    const int rg = tid & 63;
    const int rA = rg, rB = rg + 64;
    const int grA = ((rA >> 5) << 8) + j0 + (rA & 31);
    const int grB = ((rB >> 5) << 8) + j0 + (rB & 31);

    ull wA[32], wB[32];
    {
        const ulonglong2* ra = (const ulonglong2*)&whh[(size_t)grA * 256 + q * 64];
        const ulonglong2* rb = (const ulonglong2*)&whh[(size_t)grB * 256 + q * 64];
#pragma unroll
        for (int i = 0; i < 16; ++i) {
            ulonglong2 x = ra[i]; wA[2 * i] = x.x; wA[2 * i + 1] = x.y;
            ulonglong2 y = rb[i]; wB[2 * i] = y.x; wB[2 * i + 1] = y.y;
        }
    }

    for (int idx = tid; idx < 2 * NB * 256; idx += 256) ((float*)hp)[idx] = 0.f;
    if (tid == 0) {
        asm volatile("mbarrier.init.shared.b64 [%0], %1;" :: "r"(smem_u32(&mbar[0])), "r"(8));
        asm volatile("mbarrier.init.shared.b64 [%0], %1;" :: "r"(smem_u32(&mbar[1])), "r"(8));
    }
    __syncthreads();
    asm volatile("barrier.cluster.arrive.aligned;" ::: "memory");
    asm volatile("barrier.cluster.wait.aligned;" ::: "memory");

    const int cb = tid >> 5, cj = tid & 31;
    float c_state = 0.f;
    unsigned ph0 = 0, ph1 = 0;
    const uint32_t mb0 = smem_u32(&mbar[0]), mb1 = smem_u32(&mbar[1]);

    for (int t = 0; t < T_STEPS; ++t) {
        const int tr = dir ? (T_STEPS - 1 - t) : t;
        const int p = t & 1;

        float xg0 = 0.f, xg1 = 0.f, xg2 = 0.f, xg3 = 0.f;
        if (tid < CELLS) {
            size_t base = ((size_t)tr * BATCH + b0 + cb) * 1024 + j0 + cj;
            xg0 = __ldcs(&xw[base]);
            xg1 = __ldcs(&xw[base + 256]);
            xg2 = __ldcs(&xw[base + 512]);
            xg3 = __ldcs(&xw[base + 768]);
        }

        if (t > 0) {
            if (p) { mbar_wait_cluster(mb1, ph1); ph1 ^= 1; }
            else   { mbar_wait_cluster(mb0, ph0); ph0 ^= 1; }
        }

        ull accA[NB], accB[NB];
#pragma unroll
        for (int b = 0; b < NB; ++b) { accA[b] = 0ull; accB[b] = 0ull; }
        const float* hbase = &hp[p][0][q * 64];
#pragma unroll
        for (int i = 0; i < 16; ++i) {
#pragma unroll
            for (int b = 0; b < NB; ++b) {
                ulonglong2 hv = *(const ulonglong2*)(hbase + b * 256 + 4 * i);
                fma2(accA[b], wA[2 * i],     hv.x);
                fma2(accA[b], wA[2 * i + 1], hv.y);
                fma2(accB[b], wB[2 * i],     hv.x);
                fma2(accB[b], wB[2 * i + 1], hv.y);
            }
        }
#pragma unroll
        for (int b = 0; b < NB; ++b) {
            float2 a = unpack2(accA[b]); gpart[q][b][rA] = a.x + a.y;
            float2 c = unpack2(accB[b]); gpart[q][b][rB] = c.x + c.y;
        }
        __syncthreads();

        if (tid < CELLS) {
            float gi = xg0 + gpart[0][cb][cj]      + gpart[1][cb][cj]      + gpart[2][cb][cj]      + gpart[3][cb][cj];
            float gf = xg1 + gpart[0][cb][32 + cj] + gpart[1][cb][32 + cj] + gpart[2][cb][32 + cj] + gpart[3][cb][32 + cj];
            float gg = xg2 + gpart[0][cb][64 + cj] + gpart[1][cb][64 + cj] + gpart[2][cb][64 + cj] + gpart[3][cb][64 + cj];
            float go = xg3 + gpart[0][cb][96 + cj] + gpart[1][cb][96 + cj] + gpart[2][cb][96 + cj] + gpart[3][cb][96 + cj];
            float ii = sigf(gi), ff = sigf(gf), oo = sigf(go);
            c_state = ff * c_state + ii * tanhf_fast(gg);
            float h = oo * tanhf_fast(c_state);
            stage[cb][cj] = h;
            if (LAYER == 0) {
                size_t oidx = ((size_t)tr * BATCH + (b0 + cb)) * 512 + (dir << 8) + j0 + cj;
                out[oidx] = h;
                bf16 hh, hl; split1(h, hh, hl);
                outh[oidx] = hh; outl[oidx] = hl;
            } else if (t == T_STEPS - 1) {
                out[(b0 + cb) * 512 + j0 + cj] = h;
            }
        }
        if (t == T_STEPS - 1) break;
        __syncthreads();

        if (STOR == 256 || tid < STOR) {
            const int peer = tid / F4PP;
            const int i    = tid % F4PP;
            float4 val = ((const float4*)stage)[i];
            const int b  = i >> 3;
            const int jj = (i & 7) * 4;
            uint32_t laddr = smem_u32(&hp[p ^ 1][b][j0 + jj]);
            uint32_t raddr;
            asm("mapa.shared::cluster.u32 %0, %1, %2;" : "=r"(raddr) : "r"(laddr), "r"(peer));
            asm volatile("st.shared::cluster.v4.f32 [%0], {%1, %2, %3, %4};"
                         :: "r"(raddr), "f"(val.x), "f"(val.y), "f"(val.z), "f"(val.w)
                         : "memory");
        }
        __syncthreads();
        if (tid < 8) {
            uint32_t lmb = p ? mb0 : mb1;
            uint32_t rmb;
            asm("mapa.shared::cluster.u32 %0, %1, %2;" : "=r"(rmb) : "r"(lmb), "r"(tid));
            asm volatile("mbarrier.arrive.release.cluster.shared::cluster.b64 _, [%0];"
                         :: "r"(rmb) : "memory");
        }
    }
}

// ---------------- final: hb1(T-1) one-step + FC -------------------------------
__global__ void final_kernel(const float* __restrict__ fc_w, const float* __restrict__ fc_b,
                             float* __restrict__ outp)
{
    __shared__ float last[512];
    int b = blockIdx.x, tid = threadIdx.x;   // 128 threads
    for (int j = tid; j < 256; j += 128) {
        last[j] = g_LAST[b * 512 + j];
        float gi = g_XWB1L[b * 1024 + j];
        float gg = g_XWB1L[b * 1024 + 512 + j];
        float go = g_XWB1L[b * 1024 + 768 + j];
        float c = sigf(gi) * tanhf_fast(gg);
        last[256 + j] = sigf(go) * tanhf_fast(c);
    }
    __syncthreads();
    float acc = fc_b[tid];
    const float4* w  = (const float4*)&fc_w[(size_t)tid * 512];
    const float4* l4 = (const float4*)last;
#pragma unroll 8
    for (int k = 0; k < 128; ++k) {
        float4 ww = w[k]; float4 ll = l4[k];
        acc += ww.x * ll.x + ww.y * ll.y + ww.z * ll.z + ww.w * ll.w;
    }
    outp[b * 128 + tid] = acc;
}

// ---------------- launch ------------------------------------------------------
extern "C" void kernel_launch(void* const* d_in, const int* in_sizes, int n_in,
                              void* d_out, int out_size)
{
    const float* x     = (const float*)d_in[0];
    const float* wih0f = (const float*)d_in[1];
    const float* whh0f = (const float*)d_in[2];
    const float* b0f   = (const float*)d_in[3];
    const float* wih0b = (const float*)d_in[4];
    const float* whh0b = (const float*)d_in[5];
    const float* b0b   = (const float*)d_in[6];
    const float* wih1f = (const float*)d_in[7];
    const float* whh1f = (const float*)d_in[8];
    const float* b1f   = (const float*)d_in[9];
    const float* wih1b = (const float*)d_in[10];
    const float* whh1b = (const float*)d_in[11];
    const float* b1b   = (const float*)d_in[12];
    const float* fcw   = (const float*)d_in[13];
    const float* fcb   = (const float*)d_in[14];
    float* outp = (float*)d_out;

    float *XWA, *XWB, *OUT0, *LAST, *XWB1L;
    bf16 *A0H, *A0L, *O0H, *O0L, *W0FH, *W0FL, *W0BH, *W0BL, *W1FH, *W1FL;
    cudaGetSymbolAddress((void**)&XWA,   g_XWA);
    cudaGetSymbolAddress((void**)&XWB,   g_XWB);
    cudaGetSymbolAddress((void**)&OUT0,  g_OUT0);
    cudaGetSymbolAddress((void**)&LAST,  g_LAST);
    cudaGetSymbolAddress((void**)&XWB1L, g_XWB1L);
    cudaGetSymbolAddress((void**)&A0H,  g_A0H);
    cudaGetSymbolAddress((void**)&A0L,  g_A0L);
    cudaGetSymbolAddress((void**)&O0H,  g_O0H);
    cudaGetSymbolAddress((void**)&O0L,  g_O0L);
    cudaGetSymbolAddress((void**)&W0FH, g_W0FH);
    cudaGetSymbolAddress((void**)&W0FL, g_W0FL);
    cudaGetSymbolAddress((void**)&W0BH, g_W0BH);
    cudaGetSymbolAddress((void**)&W0BL, g_W0BL);
    cudaGetSymbolAddress((void**)&W1FH, g_W1FH);
    cudaGetSymbolAddress((void**)&W1FL, g_W1FL);

    const int GEMM_SMEM = 82 * 1024;
    cudaFuncSetAttribute(gemm_mma, cudaFuncAttributeMaxDynamicSharedMemorySize, GEMM_SMEM);

    // 1) transpose+split x -> A0 hi/lo
    {
        dim3 tb(32, 8);
        dim3 tg(T_STEPS / 32, INF / 32, BATCH);
        transpose_x<<<tg, tb>>>(x, A0H, A0L);
    }
    // 1b) split weights
    split_bf16<<<(1024 * 128 + 255) / 256, 256>>>(wih0f, W0FH, W0FL, 1024 * 128);
    split_bf16<<<(1024 * 128 + 255) / 256, 256>>>(wih0b, W0BH, W0BL, 1024 * 128);
    split_bf16<<<(1024 * 512 + 255) / 256, 256>>>(wih1f, W1FH, W1FL, 1024 * 512);

    // 2) layer-0 input projections (HMMA split-bf16)
    {
        dim3 gb(1024 / 128, (T_STEPS * BATCH) / 128);
        gemm_mma<<<gb, 256, GEMM_SMEM>>>(A0H, A0L, W0FH, W0FL, b0f, XWA, INF, 1024);
        gemm_mma<<<gb, 256, GEMM_SMEM>>>(A0H, A0L, W0BH, W0BL, b0b, XWB, INF, 1024);
    }
    // 3) layer-0 bidirectional recurrence -> OUT0 (+ bf16 planes)
    rec_kernel<0><<<128, 256>>>(XWA, XWB, whh0f, whh0b, OUT0, O0H, O0L);
    // 4) layer-1 fwd input projection (K=512, HMMA)
    {
        dim3 gb(1024 / 128, (T_STEPS * BATCH) / 128);
        gemm_mma<<<gb, 256, GEMM_SMEM>>>(O0H, O0L, W1FH, W1FL, b1f, XWA, 512, 1024);
    }
    // 5) layer-1 fwd recurrence -> g_LAST cols 0:256
    rec_kernel<1><<<128, 256>>>(XWA, XWA, whh1f, whh1f, LAST, nullptr, nullptr);
    // 6) layer-1 bwd FIRST step only (t = T-1): one 32-row GEMM (SIMT fp32)
    {
        dim3 gs(1024 / 128, 1);
        gemm_bias<<<gs, 256>>>(OUT0 + (size_t)(T_STEPS - 1) * BATCH * 512,
                               wih1b, b1b, XWB1L, BATCH, 1024, 512);
    }
    // 7) hb1 elementwise + FC
    final_kernel<<<BATCH, 128>>>(fcw, fcb, outp);
}

// round 7
// speedup vs baseline: 1.8127x; 1.0752x over previous
#include <cuda_runtime.h>
#include <cuda_bf16.h>
#include <math.h>
#include <cstdint>

#define T_STEPS 2048
#define BATCH 32
#define INF 128
#define HID 256

typedef unsigned long long ull;
typedef __nv_bfloat16 bf16;

// ---------------- scratch ------------------------------------------------------
__device__ float g_XWA[(size_t)T_STEPS * BATCH * 1024];
__device__ float g_XWB[(size_t)T_STEPS * BATCH * 1024];
__device__ float g_OUT0[(size_t)T_STEPS * BATCH * 512];
__device__ float g_LAST[BATCH * 512];
__device__ float g_XWB1L[BATCH * 1024];
// bf16 hi/lo planes
__device__ bf16 g_A0H[(size_t)T_STEPS * BATCH * INF];
__device__ bf16 g_A0L[(size_t)T_STEPS * BATCH * INF];
__device__ bf16 g_O0H[(size_t)T_STEPS * BATCH * 512];
__device__ bf16 g_O0L[(size_t)T_STEPS * BATCH * 512];
__device__ bf16 g_W0FH[1024 * 128], g_W0FL[1024 * 128];
__device__ bf16 g_W0BH[1024 * 128], g_W0BL[1024 * 128];
__device__ bf16 g_W1FH[1024 * 512], g_W1FL[1024 * 512];

__device__ __forceinline__ float sigf(float x) {
    return __fdividef(1.0f, 1.0f + __expf(-x));
}
__device__ __forceinline__ float tanhf_fast(float x) {
    float e = __expf(2.0f * x);
    return 1.0f - __fdividef(2.0f, e + 1.0f);
}
__device__ __forceinline__ uint32_t smem_u32(const void* p) {
    uint32_t a;
    asm("{ .reg .u64 t; cvta.to.shared.u64 t, %1; cvt.u32.u64 %0, t; }" : "=r"(a) : "l"(p));
    return a;
}
__device__ __forceinline__ void mbar_wait_cluster(uint32_t addr, unsigned phase) {
    asm volatile(
        "{\n\t.reg .pred P;\n\t"
        "WAIT_%=:\n\t"
        "mbarrier.try_wait.parity.acquire.cluster.shared::cta.b64 P, [%0], %1, 0x989680;\n\t"
        "@P bra.uni DONE_%=;\n\t"
        "bra.uni WAIT_%=;\n\t"
        "DONE_%=:\n\t}"
        :: "r"(addr), "r"(phase) : "memory");
}
__device__ __forceinline__ void cp16(uint32_t saddr, const void* gaddr) {
    asm volatile("cp.async.cg.shared.global [%0], [%1], 16;" :: "r"(saddr), "l"(gaddr));
}
__device__ __forceinline__ void ldsm4(uint32_t* r, uint32_t addr) {
    asm volatile("ldmatrix.sync.aligned.m8n8.x4.shared.b16 {%0,%1,%2,%3}, [%4];"
                 : "=r"(r[0]), "=r"(r[1]), "=r"(r[2]), "=r"(r[3]) : "r"(addr));
}
__device__ __forceinline__ void ldsm2t(uint32_t* r, uint32_t addr) {
    asm volatile("ldmatrix.sync.aligned.m8n8.x2.trans.shared.b16 {%0,%1}, [%2];"
                 : "=r"(r[0]), "=r"(r[1]) : "r"(addr));
}
__device__ __forceinline__ void mma_bf16(float* d, const uint32_t* a, const uint32_t* b) {
    asm volatile(
        "mma.sync.aligned.m16n8k16.row.col.f32.bf16.bf16.f32 "
        "{%0,%1,%2,%3}, {%4,%5,%6,%7}, {%8,%9}, {%0,%1,%2,%3};"
        : "+f"(d[0]), "+f"(d[1]), "+f"(d[2]), "+f"(d[3])
        : "r"(a[0]), "r"(a[1]), "r"(a[2]), "r"(a[3]), "r"(b[0]), "r"(b[1]));
}
__device__ __forceinline__ void split1(float v, bf16& h, bf16& l) {
    h = __float2bfloat16(v);
    l = __float2bfloat16(v - __bfloat162float(h));
}
__device__ __forceinline__ void pack2bf(float2 w, uint32_t& hi, uint32_t& lo) {
    bf16 h0, l0, h1, l1;
    split1(w.x, h0, l0); split1(w.y, h1, l1);
    __nv_bfloat162 hv; hv.x = h0; hv.y = h1;
    __nv_bfloat162 lv; lv.x = l0; lv.y = l1;
    hi = *(uint32_t*)&hv; lo = *(uint32_t*)&lv;
}

// ---------------- transpose x[B,1,IN,T] -> A0 hi/lo [(t*B+b), f] -----------------
__global__ void transpose_x(const float* __restrict__ x,
                            bf16* __restrict__ A0h, bf16* __restrict__ A0l) {
    __shared__ float tile[32][33];
    int b = blockIdx.z;
    int f0 = blockIdx.y * 32, t0 = blockIdx.x * 32;
    int tx = threadIdx.x, ty = threadIdx.y;
#pragma unroll
    for (int i = 0; i < 32; i += 8)
        tile[ty + i][tx] = x[((size_t)b * INF + (f0 + ty + i)) * T_STEPS + t0 + tx];
    __syncthreads();
#pragma unroll
    for (int i = 0; i < 32; i += 8) {
        float v = tile[tx][ty + i];
        size_t idx = (((size_t)(t0 + ty + i)) * BATCH + b) * INF + f0 + tx;
        bf16 h, l; split1(v, h, l);
        A0h[idx] = h; A0l[idx] = l;
    }
}

// ---------------- split f32 -> bf16 hi/lo --------------------------------------
__global__ void split_bf16(const float* __restrict__ in, bf16* __restrict__ hi,
                           bf16* __restrict__ lo, int n) {
    int i = blockIdx.x * blockDim.x + threadIdx.x;
    if (i < n) { bf16 h, l; split1(in[i], h, l); hi[i] = h; lo[i] = l; }
}

// ---------------- HMMA split-bf16 GEMM: C = A(f32~hi+lo) * W^T + bias ----------
__global__ void __launch_bounds__(256) gemm_mma(
    const bf16* __restrict__ Ah, const bf16* __restrict__ Al,
    const bf16* __restrict__ Wh, const bf16* __restrict__ Wl,
    const float* __restrict__ bias, float* __restrict__ C,
    int K, int N_total)
{
    extern __shared__ char sraw[];
    const uint32_t base = (smem_u32(sraw) + 127u) & ~127u;
    const uint32_t As = base;
    const uint32_t Bs = base + 40960u;

    const int tid = threadIdx.x;
    const int lane = tid & 31, wid = tid >> 5;
    const int wm = wid & 1, wn = wid >> 1;
    const int bm = blockIdx.y * 128, bn = blockIdx.x * 128;

    const int a_ro = ((lane >> 3) & 1) * 8 + (lane & 7);
    const int a_co = (lane >> 4) * 16;
    const int b_ro = ((lane >> 4) << 3) + (lane & 7);
    const int b_co = ((lane >> 3) & 1) * 16;

    const int c0 = tid * 2;

    float acc[4][4][4];
#pragma unroll
    for (int mt = 0; mt < 4; ++mt)
#pragma unroll
        for (int nt = 0; nt < 4; ++nt)
#pragma unroll
            for (int e = 0; e < 4; ++e) acc[mt][nt][e] = 0.f;

    const int nst = K >> 5;
    int buf = 0;

#pragma unroll
    for (int h = 0; h < 2; ++h) {
        int c = c0 + h, row = c >> 2, blk = c & 3;
        size_t ga = (size_t)(bm + row) * K + blk * 8;
        size_t gw = (size_t)(bn + row) * K + blk * 8;
        uint32_t so = (uint32_t)(row * 80 + blk * 16);
        cp16(As + so,          Ah + ga);
        cp16(As + 10240u + so, Al + ga);
        cp16(Bs + so,          Wh + gw);
        cp16(Bs + 10240u + so, Wl + gw);
    }
    asm volatile("cp.async.commit_group;");

    for (int st = 0; st < nst; ++st) {
        if (st + 1 < nst) {
            const int nb = buf ^ 1;
            const int k0 = (st + 1) * 32;
#pragma unroll
            for (int h = 0; h < 2; ++h) {
                int c = c0 + h, row = c >> 2, blk = c & 3;
                size_t ga = (size_t)(bm + row) * K + k0 + blk * 8;
                size_t gw = (size_t)(bn + row) * K + k0 + blk * 8;
                uint32_t so = (uint32_t)(nb * 20480 + row * 80 + blk * 16);
                cp16(As + so,          Ah + ga);
                cp16(As + 10240u + so, Al + ga);
                cp16(Bs + so,          Wh + gw);
                cp16(Bs + 10240u + so, Wl + gw);
            }
            asm volatile("cp.async.commit_group;");
            asm volatile("cp.async.wait_group 1;");
        } else {
            asm volatile("cp.async.wait_group 0;");
        }
        __syncthreads();

        const uint32_t Ab = As + buf * 20480u;
        const uint32_t Bb = Bs + buf * 20480u;
#pragma unroll
        for (int ks = 0; ks < 2; ++ks) {
            const uint32_t kb = ks * 32u;
            uint32_t bh[2][4], bl[2][4];
#pragma unroll
            for (int pr = 0; pr < 2; ++pr) {
                uint32_t ro = (uint32_t)((wn * 32 + pr * 16 + b_ro) * 80) + kb + b_co;
                ldsm4(bh[pr], Bb + ro);
                ldsm4(bl[pr], Bb + 10240u + ro);
            }
#pragma unroll
            for (int mt = 0; mt < 4; ++mt) {
                uint32_t ah[4], al[4];
                uint32_t ro = (uint32_t)((wm * 64 + mt * 16 + a_ro) * 80) + kb + a_co;
                ldsm4(ah, Ab + ro);
                ldsm4(al, Ab + 10240u + ro);
#pragma unroll
                for (int nt = 0; nt < 4; ++nt) {
                    const uint32_t* bfh = &bh[nt >> 1][(nt & 1) * 2];
                    const uint32_t* bfl = &bl[nt >> 1][(nt & 1) * 2];
                    mma_bf16(acc[mt][nt], ah, bfh);
                    mma_bf16(acc[mt][nt], al, bfh);
                    mma_bf16(acc[mt][nt], ah, bfl);
                }
            }
        }
        __syncthreads();
        buf ^= 1;
    }

    const int g = lane >> 2, tg = lane & 3;
#pragma unroll
    for (int nt = 0; nt < 4; ++nt) {
        const int col = bn + wn * 32 + nt * 8 + tg * 2;
        const float b0 = bias[col], b1 = bias[col + 1];
#pragma unroll
        for (int mt = 0; mt < 4; ++mt) {
            const int row = bm + wm * 64 + mt * 16 + g;
            float2 v0 = make_float2(acc[mt][nt][0] + b0, acc[mt][nt][1] + b1);
            float2 v1 = make_float2(acc[mt][nt][2] + b0, acc[mt][nt][3] + b1);
            *(float2*)&C[(size_t)row * N_total + col] = v0;
            *(float2*)&C[(size_t)(row + 8) * N_total + col] = v1;
        }
    }
}

// ---------------- small SIMT GEMM (32-row layer1-bwd projection) ----------------
__global__ void __launch_bounds__(256) gemm_bias(
    const float* __restrict__ A, const float* __restrict__ W,
    const float* __restrict__ bias, float* __restrict__ C,
    int M, int N, int K)
{
    __shared__ float As[16][132];
    __shared__ float Bs[16][132];
    const int bn = blockIdx.x * 128;
    const int bm = blockIdx.y * 128;
    const int tid = threadIdx.x;
    const int tx = tid & 15, ty = tid >> 4;
    const int lrow = tid >> 2;
    const int lk = (tid & 3) << 2;

    float acc[8][8];
#pragma unroll
    for (int i = 0; i < 8; i++)
#pragma unroll
        for (int j = 0; j < 8; j++) acc[i][j] = 0.f;

    for (int k0 = 0; k0 < K; k0 += 16) {
#pragma unroll
        for (int h = 0; h < 2; ++h) {
            int m = bm + lrow + h * 64;
            float4 v = (m < M) ? *(const float4*)&A[(size_t)m * K + k0 + lk]
                               : make_float4(0.f, 0.f, 0.f, 0.f);
            As[lk + 0][lrow + h * 64] = v.x; As[lk + 1][lrow + h * 64] = v.y;
            As[lk + 2][lrow + h * 64] = v.z; As[lk + 3][lrow + h * 64] = v.w;
            int n = bn + lrow + h * 64;
            float4 wv = *(const float4*)&W[(size_t)n * K + lk + k0];
            Bs[lk + 0][lrow + h * 64] = wv.x; Bs[lk + 1][lrow + h * 64] = wv.y;
            Bs[lk + 2][lrow + h * 64] = wv.z; Bs[lk + 3][lrow + h * 64] = wv.w;
        }
        __syncthreads();
#pragma unroll
        for (int k = 0; k < 16; ++k) {
            float a[8], bb[8];
            *(float4*)&a[0]  = *(const float4*)&As[k][ty * 8];
            *(float4*)&a[4]  = *(const float4*)&As[k][ty * 8 + 4];
            *(float4*)&bb[0] = *(const float4*)&Bs[k][tx * 8];
            *(float4*)&bb[4] = *(const float4*)&Bs[k][tx * 8 + 4];
#pragma unroll
            for (int i = 0; i < 8; i++)
#pragma unroll
                for (int j = 0; j < 8; j++) acc[i][j] += a[i] * bb[j];
        }
        __syncthreads();
    }
#pragma unroll
    for (int i = 0; i < 8; i++) {
        int row = bm + ty * 8 + i;
        if (row >= M) continue;
#pragma unroll
        for (int j = 0; j < 8; j += 4) {
            int col = bn + tx * 8 + j;
            float4 o;
            o.x = acc[i][j + 0] + bias[col + 0];
            o.y = acc[i][j + 1] + bias[col + 1];
            o.z = acc[i][j + 2] + bias[col + 2];
            o.w = acc[i][j + 3] + bias[col + 3];
            *(float4*)&C[(size_t)row * N + col] = o;
        }
    }
}

// ---------------- cluster recurrence, HMMA matvec --------------------------------
// 16 clusters x 8 CTAs; CTA rank = 32-unit chunk (128 gate rows). Per step per CTA:
// gates^T[128][8] = W[128][256] x H[256][8], H cols = (batch, hi/lo) pairs in bf16.
// W_hh pre-split into register-resident MMA A-fragments (Wh, Wl). Two MMA passes
// give WhHh + WhHl + WlHh. h exchange: packed u32 (hi,lo) per unit, DSMEM scatter,
// R4-proven 3-sync + count-8 arrive protocol.
template <int LAYER>
__global__ void __cluster_dims__(8, 1, 1) __launch_bounds__(256, 1) rec_kernel(
    const float* __restrict__ xwF, const float* __restrict__ xwB,
    const float* __restrict__ whhF, const float* __restrict__ whhB,
    float* __restrict__ out, bf16* __restrict__ outh, bf16* __restrict__ outl)
{
    constexpr int NB    = (LAYER == 0) ? 4 : 2;
    constexpr int CELLS = NB * 32;

    __shared__ alignas(16) bf16 hsm[2][256][8];      // [parity][k(=unit)][8 cols]
    __shared__ float gsm[4][136];                     // [batch][gate-row], pad 136
    __shared__ alignas(16) uint32_t stage[32][4];     // [unit][batch] packed (hi,lo)
    __shared__ alignas(8) unsigned long long mbar[2];

    const int tid  = threadIdx.x;
    const int lane = tid & 31, wid = tid >> 5;
    const unsigned rank = blockIdx.x & 7;
    const unsigned cl   = blockIdx.x >> 3;

    int dir, b0;
    if (LAYER == 0) { dir = cl >> 3; b0 = (cl & 7) * NB; }
    else            { dir = 0;       b0 = cl * NB; }
    const int j0 = rank * 32;

    const float* xw  = dir ? xwB  : xwF;
    const float* whh = dir ? whhB : whhF;

    // ---- W_hh -> register A-fragments (hi & lo planes), m-tile = wid ----
    const int r0 = wid * 16 + (lane >> 2);
    const int r1 = r0 + 8;
    const int gr0 = ((r0 >> 5) << 8) + j0 + (r0 & 31);
    const int gr1 = ((r1 >> 5) << 8) + j0 + (r1 & 31);
    uint32_t wh[16][4], wl[16][4];
#pragma unroll
    for (int ks = 0; ks < 16; ++ks) {
        const int k = ks * 16 + (lane & 3) * 2;
        pack2bf(*(const float2*)&whh[(size_t)gr0 * 256 + k],     wh[ks][0], wl[ks][0]);
        pack2bf(*(const float2*)&whh[(size_t)gr1 * 256 + k],     wh[ks][1], wl[ks][1]);
        pack2bf(*(const float2*)&whh[(size_t)gr0 * 256 + k + 8], wh[ks][2], wl[ks][2]);
        pack2bf(*(const float2*)&whh[(size_t)gr1 * 256 + k + 8], wh[ks][3], wl[ks][3]);
    }

    // zero h buffers (both parities; also zeroes L1's unused cols)
    for (int idx = tid; idx < 2 * 256 * 2; idx += 256)
        ((uint32_t*)hsm)[idx * 2] = 0, ((uint32_t*)hsm)[idx * 2 + 1] = 0;
    if (tid == 0) {
        asm volatile("mbarrier.init.shared.b64 [%0], %1;" :: "r"(smem_u32(&mbar[0])), "r"(8));
        asm volatile("mbarrier.init.shared.b64 [%0], %1;" :: "r"(smem_u32(&mbar[1])), "r"(8));
    }
    __syncthreads();
    asm volatile("barrier.cluster.arrive.aligned;" ::: "memory");
    asm volatile("barrier.cluster.wait.aligned;" ::: "memory");

    const int cb = tid >> 5, cj = tid & 31;
    float c_state = 0.f;
    unsigned ph0 = 0, ph1 = 0;
    const uint32_t mb0 = smem_u32(&mbar[0]), mb1 = smem_u32(&mbar[1]);
    const uint32_t hs_base = smem_u32(&hsm[0][0][0]);
    const uint32_t lrow16 = (uint32_t)(lane & 15) * 16u;

    for (int t = 0; t < T_STEPS; ++t) {
        const int tr = dir ? (T_STEPS - 1 - t) : t;
        const int p = t & 1;

        // prefetch xw gates (hidden behind wait + matvec)
        float xg0 = 0.f, xg1 = 0.f, xg2 = 0.f, xg3 = 0.f;
        if (tid < CELLS) {
            size_t base = ((size_t)tr * BATCH + b0 + cb) * 1024 + j0 + cj;
            xg0 = __ldcs(&xw[base]);
            xg1 = __ldcs(&xw[base + 256]);
            xg2 = __ldcs(&xw[base + 512]);
            xg3 = __ldcs(&xw[base + 768]);
        }

        if (t > 0) {
            if (p) { mbar_wait_cluster(mb1, ph1); ph1 ^= 1; }
            else   { mbar_wait_cluster(mb0, ph0); ph0 ^= 1; }
        }

        // ---- HMMA matvec: 16 ldsm + 32 mma per warp ----
        const uint32_t hb = hs_base + (uint32_t)p * 4096u + lrow16;
        uint32_t bb[16][2];
#pragma unroll
        for (int ks = 0; ks < 16; ++ks)
            ldsm2t(bb[ks], hb + (uint32_t)ks * 256u);
        float d[4] = {0.f, 0.f, 0.f, 0.f};
        float e[4] = {0.f, 0.f, 0.f, 0.f};
#pragma unroll
        for (int ks = 0; ks < 16; ++ks) {
            mma_bf16(d, wh[ks], bb[ks]);
            mma_bf16(e, wl[ks], bb[ks]);
        }
        // reduce: gate(row, b) = WhHh + WhHl + WlHh
        {
            const int b = lane & 3;
            const int row = wid * 16 + (lane >> 2);
            gsm[b][row]     = d[0] + d[1] + e[0];
            gsm[b][row + 8] = d[2] + d[3] + e[2];
        }
        __syncthreads();

        // ---- cell update ----
        if (tid < CELLS) {
            float gi = xg0 + gsm[cb][cj];
            float gf = xg1 + gsm[cb][32 + cj];
            float gg = xg2 + gsm[cb][64 + cj];
            float go = xg3 + gsm[cb][96 + cj];
            float ii = sigf(gi), ff = sigf(gf), oo = sigf(go);
            c_state = ff * c_state + ii * tanhf_fast(gg);
            float h = oo * tanhf_fast(c_state);
            bf16 hh, hl; split1(h, hh, hl);
            __nv_bfloat162 pv; pv.x = hh; pv.y = hl;
            stage[cj][cb] = *(uint32_t*)&pv;
            if (LAYER == 0) {
                size_t oidx = ((size_t)tr * BATCH + (b0 + cb)) * 512 + (dir << 8) + j0 + cj;
                out[oidx] = h;
                outh[oidx] = hh; outl[oidx] = hl;
            } else if (t == T_STEPS - 1) {
                out[(b0 + cb) * 512 + j0 + cj] = h;
            }
        }
        if (t == T_STEPS - 1) break;
        __syncthreads();

        // ---- DSMEM scatter: 8 peers x 32 unit-rows ----
        {
            const int peer = tid >> 5, u = tid & 31;
            uint32_t laddr = smem_u32(&hsm[p ^ 1][j0 + u][0]);
            uint32_t raddr;
            asm("mapa.shared::cluster.u32 %0, %1, %2;" : "=r"(raddr) : "r"(laddr), "r"(peer));
            if (LAYER == 0) {
                uint4 v = *(const uint4*)stage[u];
                asm volatile("st.shared::cluster.v4.b32 [%0], {%1, %2, %3, %4};"
                             :: "r"(raddr), "r"(v.x), "r"(v.y), "r"(v.z), "r"(v.w) : "memory");
            } else {
                uint2 v = *(const uint2*)&stage[u][0];
                asm volatile("st.shared::cluster.v2.b32 [%0], {%1, %2};"
                             :: "r"(raddr), "r"(v.x), "r"(v.y) : "memory");
            }
        }
        __syncthreads();
        if (tid < 8) {
            uint32_t lmb = p ? mb0 : mb1;
            uint32_t rmb;
            asm("mapa.shared::cluster.u32 %0, %1, %2;" : "=r"(rmb) : "r"(lmb), "r"(tid));
            asm volatile("mbarrier.arrive.release.cluster.shared::cluster.b64 _, [%0];"
                         :: "r"(rmb) : "memory");
        }
    }
}

// ---------------- final: hb1(T-1) one-step + FC -------------------------------
__global__ void final_kernel(const float* __restrict__ fc_w, const float* __restrict__ fc_b,
                             float* __restrict__ outp)
{
    __shared__ float last[512];
    int b = blockIdx.x, tid = threadIdx.x;   // 128 threads
    for (int j = tid; j < 256; j += 128) {
        last[j] = g_LAST[b * 512 + j];
        float gi = g_XWB1L[b * 1024 + j];
        float gg = g_XWB1L[b * 1024 + 512 + j];
        float go = g_XWB1L[b * 1024 + 768 + j];
        float c = sigf(gi) * tanhf_fast(gg);
        last[256 + j] = sigf(go) * tanhf_fast(c);
    }
    __syncthreads();
    float acc = fc_b[tid];
    const float4* w  = (const float4*)&fc_w[(size_t)tid * 512];
    const float4* l4 = (const float4*)last;
#pragma unroll 8
    for (int k = 0; k < 128; ++k) {
        float4 ww = w[k]; float4 ll = l4[k];
        acc += ww.x * ll.x + ww.y * ll.y + ww.z * ll.z + ww.w * ll.w;
    }
    outp[b * 128 + tid] = acc;
}

// ---------------- launch ------------------------------------------------------
extern "C" void kernel_launch(void* const* d_in, const int* in_sizes, int n_in,
                              void* d_out, int out_size)
{
    const float* x     = (const float*)d_in[0];
    const float* wih0f = (const float*)d_in[1];
    const float* whh0f = (const float*)d_in[2];
    const float* b0f   = (const float*)d_in[3];
    const float* wih0b = (const float*)d_in[4];
    const float* whh0b = (const float*)d_in[5];
    const float* b0b   = (const float*)d_in[6];
    const float* wih1f = (const float*)d_in[7];
    const float* whh1f = (const float*)d_in[8];
    const float* b1f   = (const float*)d_in[9];
    const float* wih1b = (const float*)d_in[10];
    const float* whh1b = (const float*)d_in[11];
    const float* b1b   = (const float*)d_in[12];
    const float* fcw   = (const float*)d_in[13];
    const float* fcb   = (const float*)d_in[14];
    float* outp = (float*)d_out;

    float *XWA, *XWB, *OUT0, *LAST, *XWB1L;
    bf16 *A0H, *A0L, *O0H, *O0L, *W0FH, *W0FL, *W0BH, *W0BL, *W1FH, *W1FL;
    cudaGetSymbolAddress((void**)&XWA,   g_XWA);
    cudaGetSymbolAddress((void**)&XWB,   g_XWB);
    cudaGetSymbolAddress((void**)&OUT0,  g_OUT0);
    cudaGetSymbolAddress((void**)&LAST,  g_LAST);
    cudaGetSymbolAddress((void**)&XWB1L, g_XWB1L);
    cudaGetSymbolAddress((void**)&A0H,  g_A0H);
    cudaGetSymbolAddress((void**)&A0L,  g_A0L);
    cudaGetSymbolAddress((void**)&O0H,  g_O0H);
    cudaGetSymbolAddress((void**)&O0L,  g_O0L);
    cudaGetSymbolAddress((void**)&W0FH, g_W0FH);
    cudaGetSymbolAddress((void**)&W0FL, g_W0FL);
    cudaGetSymbolAddress((void**)&W0BH, g_W0BH);
    cudaGetSymbolAddress((void**)&W0BL, g_W0BL);
    cudaGetSymbolAddress((void**)&W1FH, g_W1FH);
    cudaGetSymbolAddress((void**)&W1FL, g_W1FL);

    const int GEMM_SMEM = 82 * 1024;
    cudaFuncSetAttribute(gemm_mma, cudaFuncAttributeMaxDynamicSharedMemorySize, GEMM_SMEM);

    // 1) transpose+split x -> A0 hi/lo
    {
        dim3 tb(32, 8);
        dim3 tg(T_STEPS / 32, INF / 32, BATCH);
        transpose_x<<<tg, tb>>>(x, A0H, A0L);
    }
    // 1b) split weights
    split_bf16<<<(1024 * 128 + 255) / 256, 256>>>(wih0f, W0FH, W0FL, 1024 * 128);
    split_bf16<<<(1024 * 128 + 255) / 256, 256>>>(wih0b, W0BH, W0BL, 1024 * 128);
    split_bf16<<<(1024 * 512 + 255) / 256, 256>>>(wih1f, W1FH, W1FL, 1024 * 512);

    // 2) layer-0 input projections (HMMA split-bf16)
    {
        dim3 gb(1024 / 128, (T_STEPS * BATCH) / 128);
        gemm_mma<<<gb, 256, GEMM_SMEM>>>(A0H, A0L, W0FH, W0FL, b0f, XWA, INF, 1024);
        gemm_mma<<<gb, 256, GEMM_SMEM>>>(A0H, A0L, W0BH, W0BL, b0b, XWB, INF, 1024);
    }
    // 3) layer-0 bidirectional recurrence (HMMA) -> OUT0 (+ bf16 planes)
    rec_kernel<0><<<128, 256>>>(XWA, XWB, whh0f, whh0b, OUT0, O0H, O0L);
    // 4) layer-1 fwd input projection (K=512, HMMA)
    {
        dim3 gb(1024 / 128, (T_STEPS * BATCH) / 128);
        gemm_mma<<<gb, 256, GEMM_SMEM>>>(O0H, O0L, W1FH, W1FL, b1f, XWA, 512, 1024);
    }
    // 5) layer-1 fwd recurrence (HMMA) -> g_LAST cols 0:256
    rec_kernel<1><<<128, 256>>>(XWA, XWA, whh1f, whh1f, LAST, nullptr, nullptr);
    // 6) layer-1 bwd FIRST step only (t = T-1): one 32-row GEMM (SIMT fp32)
    {
        dim3 gs(1024 / 128, 1);
        gemm_bias<<<gs, 256>>>(OUT0 + (size_t)(T_STEPS - 1) * BATCH * 512,
                               wih1b, b1b, XWB1L, BATCH, 1024, 512);
    }
    // 7) hb1 elementwise + FC
    final_kernel<<<BATCH, 128>>>(fcw, fcb, outp);
}